// round 1
// baseline (speedup 1.0000x reference)
#include <cuda_runtime.h>
#include <math_constants.h>

// Problem constants: B=4, C=256, H=W=64 -> N=4096 pixels, Cqk=C/8=32
#define BB    4
#define CC    256
#define CQK   32
#define NPIX  4096
#define MTOT  (CQK + CQK + CC)   // 320 stacked output channels for fused QKV

// Scratch (no cudaMalloc allowed): q [B,32,N], k [B,32,N], v [B,C,N]
__device__ float g_q[BB * CQK * NPIX];
__device__ float g_k[BB * CQK * NPIX];
__device__ float g_v[BB * CC * NPIX];

// ---------------------------------------------------------------------------
// K1: fused QKV projection.  out[o][n] = sum_c W[o][c] * x[b][c][n] + bias[o]
// Stacked M=320 (q:0..31, k:32..63, v:64..319), K=256, N=4096 per batch.
// Tile 64(M) x 64(N), K-chunk 16, 4x4 microtile, 256 threads.
// ---------------------------------------------------------------------------
__global__ __launch_bounds__(256) void k_qkv(
    const float* __restrict__ x,
    const float* __restrict__ wq, const float* __restrict__ bq,
    const float* __restrict__ wk, const float* __restrict__ bk,
    const float* __restrict__ wv, const float* __restrict__ bv)
{
    __shared__ float Ws[16][64];   // [kk][m]
    __shared__ float Xs[16][64];   // [kk][n]
    const int b  = blockIdx.z;
    const int m0 = blockIdx.y * 64;
    const int n0 = blockIdx.x * 64;
    const int tid = threadIdx.x;
    const int tx = tid & 15;       // n group (4 cols)
    const int ty = tid >> 4;       // m group (4 rows)
    const float* xb = x + (size_t)b * CC * NPIX;

    float acc[4][4];
    #pragma unroll
    for (int i = 0; i < 4; i++)
        #pragma unroll
        for (int j = 0; j < 4; j++) acc[i][j] = 0.0f;

    for (int k0 = 0; k0 < CC; k0 += 16) {
        #pragma unroll
        for (int i = tid; i < 64 * 16; i += 256) {
            int mm = i >> 4, kk = i & 15;
            int o = m0 + mm, c = k0 + kk;
            float w;
            if (o < CQK)            w = wq[o * CC + c];
            else if (o < 2 * CQK)   w = wk[(o - CQK) * CC + c];
            else                    w = wv[(o - 2 * CQK) * CC + c];
            Ws[kk][mm] = w;
        }
        #pragma unroll
        for (int i = tid; i < 16 * 64; i += 256) {
            int kk = i >> 6, nn = i & 63;
            Xs[kk][nn] = xb[(size_t)(k0 + kk) * NPIX + n0 + nn];
        }
        __syncthreads();
        #pragma unroll
        for (int kk = 0; kk < 16; kk++) {
            float a[4], bv4[4];
            #pragma unroll
            for (int i = 0; i < 4; i++) a[i] = Ws[kk][ty * 4 + i];
            #pragma unroll
            for (int j = 0; j < 4; j++) bv4[j] = Xs[kk][tx * 4 + j];
            #pragma unroll
            for (int i = 0; i < 4; i++)
                #pragma unroll
                for (int j = 0; j < 4; j++)
                    acc[i][j] = fmaf(a[i], bv4[j], acc[i][j]);
        }
        __syncthreads();
    }

    #pragma unroll
    for (int i = 0; i < 4; i++) {
        int o = m0 + ty * 4 + i;
        float bias;
        float* dst;
        if (o < CQK)          { bias = bq[o];           dst = g_q + ((size_t)b * CQK + o) * NPIX; }
        else if (o < 2 * CQK) { bias = bk[o - CQK];     dst = g_k + ((size_t)b * CQK + (o - CQK)) * NPIX; }
        else                  { bias = bv[o - 2 * CQK]; dst = g_v + ((size_t)b * CC + (o - 2 * CQK)) * NPIX; }
        #pragma unroll
        for (int j = 0; j < 4; j++)
            dst[n0 + tx * 4 + j] = acc[i][j] + bias;
    }
}

// ---------------------------------------------------------------------------
// K2: energy, written TRANSPOSED straight into the at_map output region:
//   amap[b][m][n] = energy[b][n][m] = sum_{c<32} q[b][c][n] * k[b][c][m]
// K=32 fully unrolled, tile 64(m) x 64(n), 4x4 microtile. Write-bound (268MB).
// ---------------------------------------------------------------------------
__global__ __launch_bounds__(256) void k_energy(float* __restrict__ amap)
{
    __shared__ float Qs[CQK][64];  // [c][n]
    __shared__ float Ks[CQK][64];  // [c][m]
    const int b  = blockIdx.z;
    const int m0 = blockIdx.y * 64;
    const int n0 = blockIdx.x * 64;
    const int tid = threadIdx.x;
    const int tx = tid & 15;       // n group
    const int ty = tid >> 4;       // m group
    const float* qb = g_q + (size_t)b * CQK * NPIX;
    const float* kb = g_k + (size_t)b * CQK * NPIX;

    for (int i = tid; i < CQK * 64; i += 256) {
        int c = i >> 6, nn = i & 63;
        Qs[c][nn] = qb[(size_t)c * NPIX + n0 + nn];
        Ks[c][nn] = kb[(size_t)c * NPIX + m0 + nn];
    }
    __syncthreads();

    float acc[4][4];
    #pragma unroll
    for (int i = 0; i < 4; i++)
        #pragma unroll
        for (int j = 0; j < 4; j++) acc[i][j] = 0.0f;

    #pragma unroll
    for (int c = 0; c < CQK; c++) {
        float a[4], q4[4];
        #pragma unroll
        for (int i = 0; i < 4; i++) a[i] = Ks[c][ty * 4 + i];
        #pragma unroll
        for (int j = 0; j < 4; j++) q4[j] = Qs[c][tx * 4 + j];
        #pragma unroll
        for (int i = 0; i < 4; i++)
            #pragma unroll
            for (int j = 0; j < 4; j++)
                acc[i][j] = fmaf(a[i], q4[j], acc[i][j]);
    }

    float* dst = amap + ((size_t)b * NPIX + m0) * NPIX + n0;
    #pragma unroll
    for (int i = 0; i < 4; i++)
        #pragma unroll
        for (int j = 0; j < 4; j++)
            dst[(size_t)(ty * 4 + i) * NPIX + tx * 4 + j] = acc[i][j];
}

// ---------------------------------------------------------------------------
// K3: softmax in-place over each contiguous row amap[b][m][0..4095].
// (ref softmaxes energy over axis n; at_map rows are exactly that axis)
// One block (256 thr) per row; 16 elements/thread held in registers.
// ---------------------------------------------------------------------------
__global__ __launch_bounds__(256) void k_softmax(float* __restrict__ amap)
{
    const size_t row = blockIdx.x;
    float* p = amap + row * (size_t)NPIX;
    const int tid = threadIdx.x;
    const int lane = tid & 31, warp = tid >> 5;
    __shared__ float red[8];

    float v[16];
    float mx = -CUDART_INF_F;
    #pragma unroll
    for (int i = 0; i < 16; i++) {
        v[i] = p[tid + i * 256];
        mx = fmaxf(mx, v[i]);
    }
    #pragma unroll
    for (int o = 16; o > 0; o >>= 1)
        mx = fmaxf(mx, __shfl_xor_sync(0xffffffffu, mx, o));
    if (lane == 0) red[warp] = mx;
    __syncthreads();
    mx = red[0];
    #pragma unroll
    for (int w = 1; w < 8; w++) mx = fmaxf(mx, red[w]);
    __syncthreads();   // everyone done reading red before reuse

    float s = 0.0f;
    #pragma unroll
    for (int i = 0; i < 16; i++) {
        v[i] = __expf(v[i] - mx);
        s += v[i];
    }
    #pragma unroll
    for (int o = 16; o > 0; o >>= 1)
        s += __shfl_xor_sync(0xffffffffu, s, o);
    if (lane == 0) red[warp] = s;
    __syncthreads();
    float tot = 0.0f;
    #pragma unroll
    for (int w = 0; w < 8; w++) tot += red[w];
    float inv = 1.0f / tot;

    #pragma unroll
    for (int i = 0; i < 16; i++)
        p[tid + i * 256] = v[i] * inv;
}

// ---------------------------------------------------------------------------
// K4: sa GEMM + epilogue.
//   out[b][c][m] = x[b][c][m] + gamma * sum_n v[b][c][n] * amap[b][m][n]
// NT GEMM: both operands row-major with K(=n) contiguous.
// Tile 64(c) x 128(m), K-chunk 32, 4x8 microtile, 256 threads.
// smem padded to 33 to break the kk-column bank conflict.
// ---------------------------------------------------------------------------
__global__ __launch_bounds__(256) void k_out(
    const float* __restrict__ x, const float* __restrict__ gamma,
    const float* __restrict__ amap, float* __restrict__ out)
{
    __shared__ float Vs[64][33];
    __shared__ float As[128][33];
    const int b  = blockIdx.z;
    const int c0 = blockIdx.y * 64;
    const int m0 = blockIdx.x * 128;
    const int tid = threadIdx.x;
    const int tx = tid & 15;   // m group (8 cols)
    const int ty = tid >> 4;   // c group (4 rows)
    const float* vb = g_v + (size_t)b * CC * NPIX;
    const float* ab = amap + (size_t)b * NPIX * NPIX;

    float acc[4][8];
    #pragma unroll
    for (int i = 0; i < 4; i++)
        #pragma unroll
        for (int j = 0; j < 8; j++) acc[i][j] = 0.0f;

    for (int k0 = 0; k0 < NPIX; k0 += 32) {
        #pragma unroll
        for (int i = tid; i < 64 * 32; i += 256) {
            int r = i >> 5, kk = i & 31;
            Vs[r][kk] = vb[(size_t)(c0 + r) * NPIX + k0 + kk];
        }
        #pragma unroll
        for (int i = tid; i < 128 * 32; i += 256) {
            int r = i >> 5, kk = i & 31;
            As[r][kk] = ab[(size_t)(m0 + r) * NPIX + k0 + kk];
        }
        __syncthreads();
        #pragma unroll
        for (int kk = 0; kk < 32; kk++) {
            float a[4], p[8];
            #pragma unroll
            for (int i = 0; i < 4; i++) a[i] = Vs[ty * 4 + i][kk];
            #pragma unroll
            for (int j = 0; j < 8; j++) p[j] = As[tx * 8 + j][kk];
            #pragma unroll
            for (int i = 0; i < 4; i++)
                #pragma unroll
                for (int j = 0; j < 8; j++)
                    acc[i][j] = fmaf(a[i], p[j], acc[i][j]);
        }
        __syncthreads();
    }

    const float g = gamma[0];
    const float* xb = x + (size_t)b * CC * NPIX;
    float* ob = out + (size_t)b * CC * NPIX;
    #pragma unroll
    for (int i = 0; i < 4; i++) {
        #pragma unroll
        for (int j = 0; j < 8; j++) {
            size_t idx = (size_t)(c0 + ty * 4 + i) * NPIX + m0 + tx * 8 + j;
            ob[idx] = xb[idx] + g * acc[i][j];
        }
    }
}

extern "C" void kernel_launch(void* const* d_in, const int* in_sizes, int n_in,
                              void* d_out, int out_size)
{
    (void)in_sizes; (void)n_in; (void)out_size;
    const float* x     = (const float*)d_in[0];
    const float* wq    = (const float*)d_in[1];
    const float* bq    = (const float*)d_in[2];
    const float* wk    = (const float*)d_in[3];
    const float* bk    = (const float*)d_in[4];
    const float* wv    = (const float*)d_in[5];
    const float* bv    = (const float*)d_in[6];
    const float* gamma = (const float*)d_in[7];

    float* out  = (float*)d_out;                      // [B,C,H,W] = 4,194,304 floats
    float* amap = out + (size_t)BB * CC * NPIX;       // [B,N,N]   = 67,108,864 floats

    // K1: fused QKV projection
    k_qkv<<<dim3(NPIX / 64, MTOT / 64, BB), 256>>>(x, wq, bq, wk, bk, wv, bv);
    // K2: energy (transposed) -> at_map region, raw
    k_energy<<<dim3(NPIX / 64, NPIX / 64, BB), 256>>>(amap);
    // K3: softmax in place over contiguous rows
    k_softmax<<<dim3(BB * NPIX), 256>>>(amap);
    // K4: sa GEMM + residual epilogue
    k_out<<<dim3(NPIX / 128, CC / 64, BB), 256>>>(x, gamma, amap, out);
}

// round 5
// speedup vs baseline: 2.6852x; 2.6852x over previous
#include <cuda_runtime.h>
#include <cuda_bf16.h>
#include <math_constants.h>
#include <cstdint>

// Problem constants: B=4, C=256, H=W=64 -> N=4096 pixels, Cqk=C/8=32
#define BB    4
#define CC    256
#define CQK   32
#define NPIX  4096
#define MTOT  (CQK + CQK + CC)   // 320 stacked output channels for fused QKV

// Scratch (no cudaMalloc allowed):
__device__ __align__(16) float g_q[BB * CQK * NPIX];
__device__ __align__(16) float g_k[BB * CQK * NPIX];
// v split into bf16 hi/lo (written by K1, consumed by K4 tensor cores)
__device__ __align__(16) __nv_bfloat16 g_vh[BB * CC * NPIX];
__device__ __align__(16) __nv_bfloat16 g_vl[BB * CC * NPIX];
// attn split into bf16 hi/lo (written by K3, consumed by K4)
__device__ __align__(16) __nv_bfloat16 g_bh[(size_t)BB * NPIX * NPIX];
__device__ __align__(16) __nv_bfloat16 g_bl[(size_t)BB * NPIX * NPIX];

// ===========================================================================
// PTX helpers — baseline (non-'a') features only: mma.sync bf16 + cp.async.
// tcgen05/TMEM is NOT available (harness PTX targets compute_103, no 'a').
// ===========================================================================
__device__ __forceinline__ void mma16816(float* d, const uint32_t* a, const uint32_t* b) {
    asm volatile(
        "mma.sync.aligned.m16n8k16.row.col.f32.bf16.bf16.f32 "
        "{%0,%1,%2,%3}, {%4,%5,%6,%7}, {%8,%9}, {%0,%1,%2,%3};"
        : "+f"(d[0]), "+f"(d[1]), "+f"(d[2]), "+f"(d[3])
        : "r"(a[0]), "r"(a[1]), "r"(a[2]), "r"(a[3]), "r"(b[0]), "r"(b[1]));
}
__device__ __forceinline__ uint32_t smem_u32(const void* p) {
    uint32_t a;
    asm("{ .reg .u64 t; cvta.to.shared.u64 t, %1; cvt.u32.u64 %0, t; }"
        : "=r"(a) : "l"(p));
    return a;
}
__device__ __forceinline__ void cp16(uint32_t saddr, const void* g) {
    asm volatile("cp.async.cg.shared.global [%0], [%1], 16;" :: "r"(saddr), "l"(g));
}
#define CP_COMMIT() asm volatile("cp.async.commit_group;" ::: "memory")
#define CP_WAIT(n)  asm volatile("cp.async.wait_group %0;" :: "n"(n) : "memory")

// ---------------------------------------------------------------------------
// K1: fused QKV projection.  out[o][n] = sum_c W[o][c] * x[b][c][n] + bias[o]
// v channels are written as bf16 hi/lo split.
// ---------------------------------------------------------------------------
__global__ __launch_bounds__(256) void k_qkv(
    const float* __restrict__ x,
    const float* __restrict__ wq, const float* __restrict__ bq,
    const float* __restrict__ wk, const float* __restrict__ bk,
    const float* __restrict__ wv, const float* __restrict__ bv)
{
    __shared__ float Ws[16][64];   // [kk][m]
    __shared__ float Xs[16][64];   // [kk][n]
    const int b  = blockIdx.z;
    const int m0 = blockIdx.y * 64;
    const int n0 = blockIdx.x * 64;
    const int tid = threadIdx.x;
    const int tx = tid & 15;
    const int ty = tid >> 4;
    const float* xb = x + (size_t)b * CC * NPIX;

    float acc[4][4];
    #pragma unroll
    for (int i = 0; i < 4; i++)
        #pragma unroll
        for (int j = 0; j < 4; j++) acc[i][j] = 0.0f;

    for (int k0 = 0; k0 < CC; k0 += 16) {
        #pragma unroll
        for (int i = tid; i < 64 * 16; i += 256) {
            int mm = i >> 4, kk = i & 15;
            int o = m0 + mm, c = k0 + kk;
            float w;
            if (o < CQK)            w = wq[o * CC + c];
            else if (o < 2 * CQK)   w = wk[(o - CQK) * CC + c];
            else                    w = wv[(o - 2 * CQK) * CC + c];
            Ws[kk][mm] = w;
        }
        #pragma unroll
        for (int i = tid; i < 16 * 64; i += 256) {
            int kk = i >> 6, nn = i & 63;
            Xs[kk][nn] = xb[(size_t)(k0 + kk) * NPIX + n0 + nn];
        }
        __syncthreads();
        #pragma unroll
        for (int kk = 0; kk < 16; kk++) {
            float a[4], bv4[4];
            #pragma unroll
            for (int i = 0; i < 4; i++) a[i] = Ws[kk][ty * 4 + i];
            #pragma unroll
            for (int j = 0; j < 4; j++) bv4[j] = Xs[kk][tx * 4 + j];
            #pragma unroll
            for (int i = 0; i < 4; i++)
                #pragma unroll
                for (int j = 0; j < 4; j++)
                    acc[i][j] = fmaf(a[i], bv4[j], acc[i][j]);
        }
        __syncthreads();
    }

    #pragma unroll
    for (int i = 0; i < 4; i++) {
        int o = m0 + ty * 4 + i;
        if (o < CQK) {
            float bias = bq[o];
            float* dst = g_q + ((size_t)b * CQK + o) * NPIX;
            #pragma unroll
            for (int j = 0; j < 4; j++)
                dst[n0 + tx * 4 + j] = acc[i][j] + bias;
        } else if (o < 2 * CQK) {
            float bias = bk[o - CQK];
            float* dst = g_k + ((size_t)b * CQK + (o - CQK)) * NPIX;
            #pragma unroll
            for (int j = 0; j < 4; j++)
                dst[n0 + tx * 4 + j] = acc[i][j] + bias;
        } else {
            float bias = bv[o - 2 * CQK];
            size_t base = ((size_t)b * CC + (o - 2 * CQK)) * NPIX + n0;
            #pragma unroll
            for (int j = 0; j < 4; j++) {
                float val = acc[i][j] + bias;
                __nv_bfloat16 h = __float2bfloat16(val);
                __nv_bfloat16 l = __float2bfloat16(val - __bfloat162float(h));
                g_vh[base + tx * 4 + j] = h;
                g_vl[base + tx * 4 + j] = l;
            }
        }
    }
}

// ---------------------------------------------------------------------------
// K2: energy, written TRANSPOSED straight into the at_map output region:
//   amap[b][m][n] = energy[b][n][m] = sum_{c<32} q[b][c][n] * k[b][c][m]
// ---------------------------------------------------------------------------
__global__ __launch_bounds__(256) void k_energy(float* __restrict__ amap)
{
    __shared__ float Qs[CQK][64];
    __shared__ float Ks[CQK][64];
    const int b  = blockIdx.z;
    const int m0 = blockIdx.y * 64;
    const int n0 = blockIdx.x * 64;
    const int tid = threadIdx.x;
    const int tx = tid & 15;
    const int ty = tid >> 4;
    const float* qb = g_q + (size_t)b * CQK * NPIX;
    const float* kb = g_k + (size_t)b * CQK * NPIX;

    for (int i = tid; i < CQK * 64; i += 256) {
        int c = i >> 6, nn = i & 63;
        Qs[c][nn] = qb[(size_t)c * NPIX + n0 + nn];
        Ks[c][nn] = kb[(size_t)c * NPIX + m0 + nn];
    }
    __syncthreads();

    float acc[4][4];
    #pragma unroll
    for (int i = 0; i < 4; i++)
        #pragma unroll
        for (int j = 0; j < 4; j++) acc[i][j] = 0.0f;

    #pragma unroll
    for (int c = 0; c < CQK; c++) {
        float a[4], q4[4];
        #pragma unroll
        for (int i = 0; i < 4; i++) a[i] = Ks[c][ty * 4 + i];
        #pragma unroll
        for (int j = 0; j < 4; j++) q4[j] = Qs[c][tx * 4 + j];
        #pragma unroll
        for (int i = 0; i < 4; i++)
            #pragma unroll
            for (int j = 0; j < 4; j++)
                acc[i][j] = fmaf(a[i], q4[j], acc[i][j]);
    }

    float* dst = amap + ((size_t)b * NPIX + m0) * NPIX + n0;
    #pragma unroll
    for (int i = 0; i < 4; i++)
        #pragma unroll
        for (int j = 0; j < 4; j++)
            dst[(size_t)(ty * 4 + i) * NPIX + tx * 4 + j] = acc[i][j];
}

// ---------------------------------------------------------------------------
// K3: softmax in-place over each contiguous row amap[b][m][0..4095], plus
// streaming bf16 hi/lo split of the result for the tensor-core consumer.
// ---------------------------------------------------------------------------
__global__ __launch_bounds__(256) void k_softmax(float* __restrict__ amap)
{
    const size_t row = blockIdx.x;
    float* p = amap + row * (size_t)NPIX;
    __nv_bfloat16* ph = g_bh + row * (size_t)NPIX;
    __nv_bfloat16* pl = g_bl + row * (size_t)NPIX;
    const int tid = threadIdx.x;
    const int lane = tid & 31, warp = tid >> 5;
    __shared__ float red[8];

    float v[16];
    float mx = -CUDART_INF_F;
    #pragma unroll
    for (int i = 0; i < 16; i++) {
        v[i] = p[tid + i * 256];
        mx = fmaxf(mx, v[i]);
    }
    #pragma unroll
    for (int o = 16; o > 0; o >>= 1)
        mx = fmaxf(mx, __shfl_xor_sync(0xffffffffu, mx, o));
    if (lane == 0) red[warp] = mx;
    __syncthreads();
    mx = red[0];
    #pragma unroll
    for (int w = 1; w < 8; w++) mx = fmaxf(mx, red[w]);
    __syncthreads();

    float s = 0.0f;
    #pragma unroll
    for (int i = 0; i < 16; i++) {
        v[i] = __expf(v[i] - mx);
        s += v[i];
    }
    #pragma unroll
    for (int o = 16; o > 0; o >>= 1)
        s += __shfl_xor_sync(0xffffffffu, s, o);
    if (lane == 0) red[warp] = s;
    __syncthreads();
    float tot = 0.0f;
    #pragma unroll
    for (int w = 0; w < 8; w++) tot += red[w];
    float inv = 1.0f / tot;

    #pragma unroll
    for (int i = 0; i < 16; i++) {
        float a = v[i] * inv;
        p[tid + i * 256] = a;
        __nv_bfloat16 h = __float2bfloat16(a);
        __nv_bfloat16 l = __float2bfloat16(a - __bfloat162float(h));
        ph[tid + i * 256] = h;
        pl[tid + i * 256] = l;
    }
}

// ---------------------------------------------------------------------------
// K4: sa GEMM on mma.sync bf16 (3-pass split for fp32-grade accuracy).
//   out[b][c][m] = x[b][c][m] + gamma * sum_n v[b][c][n] * amap[b][m][n]
// CTA tile: 128(c) x 128(m), K(=n) chunk 32, cp.async double buffer.
// 8 warps as 2(c) x 4(m); warp tile 64(c) x 32(m); m16n8k16 fragments.
// smem pitch 40 bf16 (80B = 20 banks): fragment LDS pattern conflict-free.
// ---------------------------------------------------------------------------
#define BKC   32
#define PITCH 40
#define TILE_BYTES (128 * PITCH * 2)        // 10240
#define STAGE_B    (4 * TILE_BYTES)         // 40960: Ah | Al | Bh | Bl
#define NCH   (NPIX / BKC)                  // 128

__global__ __launch_bounds__(256) void k_out_mma(
    const float* __restrict__ x, const float* __restrict__ gamma,
    float* __restrict__ out)
{
    extern __shared__ __align__(16) char smem[];
    const int b  = blockIdx.z;
    const int c0 = blockIdx.y * 128;
    const int m0 = blockIdx.x * 128;
    const int tid = threadIdx.x;
    const int L   = tid & 31;
    const int wid = tid >> 5;
    const int wc  = (wid & 1) * 64;     // warp c-offset in tile
    const int wm  = (wid >> 1) * 32;    // warp m-offset in tile
    const int gq  = L >> 2;             // groupID
    const int tg  = L & 3;              // threadID_in_group

    const uint32_t sbase = smem_u32(smem);
    const __nv_bfloat16* vhp = g_vh + ((size_t)b * CC + c0) * NPIX;
    const __nv_bfloat16* vlp = g_vl + ((size_t)b * CC + c0) * NPIX;
    const __nv_bfloat16* bhp = g_bh + ((size_t)b * NPIX + m0) * NPIX;
    const __nv_bfloat16* blp = g_bl + ((size_t)b * NPIX + m0) * NPIX;

    // ---- async tile loader: 512 x 16B chunks per stage, 2 per thread/tile
    auto load_stage = [&](int s, int ch) {
        const int k0 = ch * BKC;
        const uint32_t st = sbase + s * STAGE_B;
        #pragma unroll
        for (int i = 0; i < 2; i++) {
            const int idx = tid + i * 256;        // 0..511
            const int row = idx >> 2;
            const int seg = idx & 3;              // 16B segment (8 bf16)
            const uint32_t so = row * (PITCH * 2) + seg * 16;
            const size_t  go = (size_t)row * NPIX + k0 + seg * 8;
            cp16(st + 0 * TILE_BYTES + so, vhp + go);
            cp16(st + 1 * TILE_BYTES + so, vlp + go);
            cp16(st + 2 * TILE_BYTES + so, bhp + go);
            cp16(st + 3 * TILE_BYTES + so, blp + go);
        }
    };

    float acc[4][4][4];
    #pragma unroll
    for (int i = 0; i < 4; i++)
        #pragma unroll
        for (int j = 0; j < 4; j++)
            #pragma unroll
            for (int r = 0; r < 4; r++) acc[i][j][r] = 0.0f;

    load_stage(0, 0);
    CP_COMMIT();

    for (int ch = 0; ch < NCH; ch++) {
        const int s = ch & 1;
        if (ch + 1 < NCH) {
            load_stage(s ^ 1, ch + 1);
            CP_COMMIT();
            CP_WAIT(1);
        } else {
            CP_WAIT(0);
        }
        __syncthreads();

        const char* st = smem + s * STAGE_B;
        const __nv_bfloat16* Ah = (const __nv_bfloat16*)(st);
        const __nv_bfloat16* Al = (const __nv_bfloat16*)(st + TILE_BYTES);
        const __nv_bfloat16* Bh = (const __nv_bfloat16*)(st + 2 * TILE_BYTES);
        const __nv_bfloat16* Bl = (const __nv_bfloat16*)(st + 3 * TILE_BYTES);

        #pragma unroll
        for (int ks = 0; ks < 2; ks++) {
            const int kb = ks * 16 + tg * 2;
            uint32_t ah[4][4], al[4][4], bh[4][2], bl[4][2];
            #pragma unroll
            for (int fc = 0; fc < 4; fc++) {
                const int r = wc + fc * 16 + gq;
                ah[fc][0] = *(const uint32_t*)&Ah[(r    ) * PITCH + kb    ];
                ah[fc][1] = *(const uint32_t*)&Ah[(r + 8) * PITCH + kb    ];
                ah[fc][2] = *(const uint32_t*)&Ah[(r    ) * PITCH + kb + 8];
                ah[fc][3] = *(const uint32_t*)&Ah[(r + 8) * PITCH + kb + 8];
                al[fc][0] = *(const uint32_t*)&Al[(r    ) * PITCH + kb    ];
                al[fc][1] = *(const uint32_t*)&Al[(r + 8) * PITCH + kb    ];
                al[fc][2] = *(const uint32_t*)&Al[(r    ) * PITCH + kb + 8];
                al[fc][3] = *(const uint32_t*)&Al[(r + 8) * PITCH + kb + 8];
            }
            #pragma unroll
            for (int fm = 0; fm < 4; fm++) {
                const int n = wm + fm * 8 + gq;
                bh[fm][0] = *(const uint32_t*)&Bh[n * PITCH + kb    ];
                bh[fm][1] = *(const uint32_t*)&Bh[n * PITCH + kb + 8];
                bl[fm][0] = *(const uint32_t*)&Bl[n * PITCH + kb    ];
                bl[fm][1] = *(const uint32_t*)&Bl[n * PITCH + kb + 8];
            }
            #pragma unroll
            for (int fc = 0; fc < 4; fc++)
                #pragma unroll
                for (int fm = 0; fm < 4; fm++) {
                    mma16816(acc[fc][fm], ah[fc], bh[fm]);
                    mma16816(acc[fc][fm], ah[fc], bl[fm]);
                    mma16816(acc[fc][fm], al[fc], bh[fm]);
                }
        }
        __syncthreads();
    }

    // ---- epilogue: out = x + gamma * acc, float2 stores
    const float gm = gamma[0];
    #pragma unroll
    for (int fc = 0; fc < 4; fc++) {
        #pragma unroll
        for (int fm = 0; fm < 4; fm++) {
            const int cr = c0 + wc + fc * 16 + gq;
            const int mc = m0 + wm + fm * 8 + tg * 2;
            {
                const size_t gi = ((size_t)b * CC + cr) * NPIX + mc;
                float2 xv = *(const float2*)&x[gi];
                float2 o;
                o.x = xv.x + gm * acc[fc][fm][0];
                o.y = xv.y + gm * acc[fc][fm][1];
                *(float2*)&out[gi] = o;
            }
            {
                const size_t gi = ((size_t)b * CC + cr + 8) * NPIX + mc;
                float2 xv = *(const float2*)&x[gi];
                float2 o;
                o.x = xv.x + gm * acc[fc][fm][2];
                o.y = xv.y + gm * acc[fc][fm][3];
                *(float2*)&out[gi] = o;
            }
        }
    }
}

extern "C" void kernel_launch(void* const* d_in, const int* in_sizes, int n_in,
                              void* d_out, int out_size)
{
    (void)in_sizes; (void)n_in; (void)out_size;
    const float* x     = (const float*)d_in[0];
    const float* wq    = (const float*)d_in[1];
    const float* bq    = (const float*)d_in[2];
    const float* wk    = (const float*)d_in[3];
    const float* bk    = (const float*)d_in[4];
    const float* wv    = (const float*)d_in[5];
    const float* bv    = (const float*)d_in[6];
    const float* gamma = (const float*)d_in[7];

    float* out  = (float*)d_out;                      // [B,C,H,W]
    float* amap = out + (size_t)BB * CC * NPIX;       // [B,N,N]

    static const int dsm = 2 * STAGE_B;               // 81920 B
    cudaFuncSetAttribute(k_out_mma, cudaFuncAttributeMaxDynamicSharedMemorySize, dsm);

    k_qkv<<<dim3(NPIX / 64, MTOT / 64, BB), 256>>>(x, wq, bq, wk, bk, wv, bv);
    k_energy<<<dim3(NPIX / 64, NPIX / 64, BB), 256>>>(amap);
    k_softmax<<<dim3(BB * NPIX), 256>>>(amap);
    k_out_mma<<<dim3(NPIX / 128, CC / 128, BB), 256, dsm>>>(x, gamma, out);
}

// round 9
// speedup vs baseline: 3.2365x; 1.2053x over previous
#include <cuda_runtime.h>
#include <cuda_bf16.h>
#include <math_constants.h>
#include <cstdint>

// Problem constants: B=4, C=256, H=W=64 -> N=4096 pixels, Cqk=C/8=32
#define BB    4
#define CC    256
#define CQK   32
#define NPIX  4096
#define MTOT  (CQK + CQK + CC)   // 320 stacked output channels for fused QKV

// Scratch (no cudaMalloc allowed):
// q,k transposed to [b][n][32] bf16 hi/lo (for K2 tensor cores)
__device__ __align__(16) __nv_bfloat16 g_qh[BB * NPIX * CQK];
__device__ __align__(16) __nv_bfloat16 g_ql[BB * NPIX * CQK];
__device__ __align__(16) __nv_bfloat16 g_kh[BB * NPIX * CQK];
__device__ __align__(16) __nv_bfloat16 g_kl[BB * NPIX * CQK];
// v split into bf16 hi/lo, [b][c][n] (for K4)
__device__ __align__(16) __nv_bfloat16 g_vh[BB * CC * NPIX];
__device__ __align__(16) __nv_bfloat16 g_vl[BB * CC * NPIX];
// attn split into bf16 hi/lo (written by K3, consumed by K4)
__device__ __align__(16) __nv_bfloat16 g_bh[(size_t)BB * NPIX * NPIX];
__device__ __align__(16) __nv_bfloat16 g_bl[(size_t)BB * NPIX * NPIX];

// ===========================================================================
// PTX helpers — baseline (non-'a') features only: mma.sync bf16, ldmatrix,
// cp.async. tcgen05/TMEM rejected by ptxas at compute_103 (no 'a').
// ===========================================================================
__device__ __forceinline__ void mma16816(float* d, const uint32_t* a, const uint32_t* b) {
    asm volatile(
        "mma.sync.aligned.m16n8k16.row.col.f32.bf16.bf16.f32 "
        "{%0,%1,%2,%3}, {%4,%5,%6,%7}, {%8,%9}, {%0,%1,%2,%3};"
        : "+f"(d[0]), "+f"(d[1]), "+f"(d[2]), "+f"(d[3])
        : "r"(a[0]), "r"(a[1]), "r"(a[2]), "r"(a[3]), "r"(b[0]), "r"(b[1]));
}
__device__ __forceinline__ void ldsm4(uint32_t* r, uint32_t addr) {
    asm volatile("ldmatrix.sync.aligned.m8n8.x4.shared.b16 {%0,%1,%2,%3}, [%4];"
        : "=r"(r[0]), "=r"(r[1]), "=r"(r[2]), "=r"(r[3]) : "r"(addr));
}
__device__ __forceinline__ uint32_t smem_u32(const void* p) {
    uint32_t a;
    asm("{ .reg .u64 t; cvta.to.shared.u64 t, %1; cvt.u32.u64 %0, t; }"
        : "=r"(a) : "l"(p));
    return a;
}
__device__ __forceinline__ void cp16(uint32_t saddr, const void* g) {
    asm volatile("cp.async.cg.shared.global [%0], [%1], 16;" :: "r"(saddr), "l"(g));
}
#define CP_COMMIT() asm volatile("cp.async.commit_group;" ::: "memory")
#define CP_WAIT(n)  asm volatile("cp.async.wait_group %0;" :: "n"(n) : "memory")

__device__ __forceinline__ void split_bf16(float v, __nv_bfloat16& h, __nv_bfloat16& l) {
    h = __float2bfloat16(v);
    l = __float2bfloat16(v - __bfloat162float(h));
}

// ---------------------------------------------------------------------------
// K1: fused QKV projection.  out[o][n] = sum_c W[o][c] * x[b][c][n] + bias[o]
// by==0 block holds all 64 q+k channels -> smem transpose -> [n][c] bf16 hi/lo.
// v channels written [c][n] bf16 hi/lo.
// ---------------------------------------------------------------------------
__global__ __launch_bounds__(256) void k_qkv(
    const float* __restrict__ x,
    const float* __restrict__ wq, const float* __restrict__ bq,
    const float* __restrict__ wk, const float* __restrict__ bk,
    const float* __restrict__ wv, const float* __restrict__ bv)
{
    __shared__ float Ws[16][64];   // [kk][m]
    __shared__ float Xs[16][64];   // [kk][n]
    __shared__ float Ts[64][65];   // transpose staging for q/k block
    const int b  = blockIdx.z;
    const int m0 = blockIdx.y * 64;
    const int n0 = blockIdx.x * 64;
    const int tid = threadIdx.x;
    const int tx = tid & 15;
    const int ty = tid >> 4;
    const float* xb = x + (size_t)b * CC * NPIX;

    float acc[4][4];
    #pragma unroll
    for (int i = 0; i < 4; i++)
        #pragma unroll
        for (int j = 0; j < 4; j++) acc[i][j] = 0.0f;

    for (int k0 = 0; k0 < CC; k0 += 16) {
        #pragma unroll
        for (int i = tid; i < 64 * 16; i += 256) {
            int mm = i >> 4, kk = i & 15;
            int o = m0 + mm, c = k0 + kk;
            float w;
            if (o < CQK)            w = wq[o * CC + c];
            else if (o < 2 * CQK)   w = wk[(o - CQK) * CC + c];
            else                    w = wv[(o - 2 * CQK) * CC + c];
            Ws[kk][mm] = w;
        }
        #pragma unroll
        for (int i = tid; i < 16 * 64; i += 256) {
            int kk = i >> 6, nn = i & 63;
            Xs[kk][nn] = xb[(size_t)(k0 + kk) * NPIX + n0 + nn];
        }
        __syncthreads();
        #pragma unroll
        for (int kk = 0; kk < 16; kk++) {
            float a[4], bv4[4];
            #pragma unroll
            for (int i = 0; i < 4; i++) a[i] = Ws[kk][ty * 4 + i];
            #pragma unroll
            for (int j = 0; j < 4; j++) bv4[j] = Xs[kk][tx * 4 + j];
            #pragma unroll
            for (int i = 0; i < 4; i++)
                #pragma unroll
                for (int j = 0; j < 4; j++)
                    acc[i][j] = fmaf(a[i], bv4[j], acc[i][j]);
        }
        __syncthreads();
    }

    if (blockIdx.y == 0) {
        // q (o 0..31) + k (o 32..63): stage with bias, transpose, split bf16
        #pragma unroll
        for (int i = 0; i < 4; i++) {
            int o = ty * 4 + i;
            float bias = (o < CQK) ? bq[o] : bk[o - CQK];
            #pragma unroll
            for (int j = 0; j < 4; j++)
                Ts[o][tx * 4 + j] = acc[i][j] + bias;
        }
        __syncthreads();
        if (tid < 128) {
            const int half = tid >> 6;      // 0=q, 1=k
            const int nloc = tid & 63;
            __nv_bfloat16 hb[32], lb[32];
            #pragma unroll
            for (int c = 0; c < 32; c++)
                split_bf16(Ts[half * 32 + c][nloc], hb[c], lb[c]);
            __nv_bfloat16* dh = (half ? g_kh : g_qh) + ((size_t)b * NPIX + n0 + nloc) * CQK;
            __nv_bfloat16* dl = (half ? g_kl : g_ql) + ((size_t)b * NPIX + n0 + nloc) * CQK;
            #pragma unroll
            for (int q = 0; q < 4; q++) {
                *(uint4*)(dh + q * 8) = *(const uint4*)(hb + q * 8);
                *(uint4*)(dl + q * 8) = *(const uint4*)(lb + q * 8);
            }
        }
    } else {
        #pragma unroll
        for (int i = 0; i < 4; i++) {
            int c = m0 - 2 * CQK + ty * 4 + i;
            float bias = bv[c];
            size_t base = ((size_t)b * CC + c) * NPIX + n0;
            #pragma unroll
            for (int j = 0; j < 4; j++) {
                float val = acc[i][j] + bias;
                __nv_bfloat16 h, l;
                split_bf16(val, h, l);
                g_vh[base + tx * 4 + j] = h;
                g_vl[base + tx * 4 + j] = l;
            }
        }
    }
}

// ---------------------------------------------------------------------------
// K2: energy on mma.sync bf16 (3-pass split), written transposed into at_map:
//   amap[b][m][n] = sum_c kT[m][c] * qT[n][c]
// CTA tile 128(m) x 128(n), K=32 (2 k-steps). ldmatrix fragment loads.
// ---------------------------------------------------------------------------
#define PITCH 40   // bf16 elements per smem row (80B) — conflict-free ldmatrix

__global__ __launch_bounds__(256) void k_energy_mma(float* __restrict__ amap)
{
    __shared__ __align__(16) __nv_bfloat16 Kh[128 * PITCH], Kl[128 * PITCH];
    __shared__ __align__(16) __nv_bfloat16 Qh[128 * PITCH], Ql[128 * PITCH];
    const int b  = blockIdx.z;
    const int m0 = blockIdx.y * 128;
    const int n0 = blockIdx.x * 128;
    const int tid = threadIdx.x;
    const int L   = tid & 31;
    const int wid = tid >> 5;
    const int wc  = (wid & 1) * 64;     // warp m-offset
    const int wn  = (wid >> 1) * 32;    // warp n-offset
    const int gq  = L >> 2;
    const int tg  = L & 3;

    const uint32_t uKh = smem_u32(Kh), uKl = smem_u32(Kl);
    const uint32_t uQh = smem_u32(Qh), uQl = smem_u32(Ql);

    // load 4 tiles: 128 rows x 64B each
    #pragma unroll
    for (int t = 0; t < 2; t++) {
        const int idx = tid + t * 256;
        const int row = idx >> 2, seg = idx & 3;
        const uint32_t so = row * (PITCH * 2) + seg * 16;
        const size_t km = ((size_t)b * NPIX + m0 + row) * CQK + seg * 8;
        const size_t qn = ((size_t)b * NPIX + n0 + row) * CQK + seg * 8;
        cp16(uKh + so, g_kh + km);
        cp16(uKl + so, g_kl + km);
        cp16(uQh + so, g_qh + qn);
        cp16(uQl + so, g_ql + qn);
    }
    CP_COMMIT(); CP_WAIT(0);
    __syncthreads();

    const uint32_t arow = (L & 15) * (PITCH * 2) + ((L >> 4) * 16);
    const uint32_t brow = ((L & 7) + ((L >> 4) << 3)) * (PITCH * 2) + (((L >> 3) & 1) * 16);

    float acc[4][4][4];
    #pragma unroll
    for (int i = 0; i < 4; i++)
        #pragma unroll
        for (int j = 0; j < 4; j++)
            #pragma unroll
            for (int r = 0; r < 4; r++) acc[i][j][r] = 0.0f;

    #pragma unroll
    for (int ks = 0; ks < 2; ks++) {
        const uint32_t colB = ks * 32;
        uint32_t ah[4][4], al[4][4], bh4[2][4], bl4[2][4];
        #pragma unroll
        for (int fc = 0; fc < 4; fc++) {
            const uint32_t ro = (wc + fc * 16) * (PITCH * 2) + arow + colB;
            ldsm4(ah[fc], uKh + ro);
            ldsm4(al[fc], uKl + ro);
        }
        #pragma unroll
        for (int p = 0; p < 2; p++) {
            const uint32_t ro = (wn + p * 16) * (PITCH * 2) + brow + colB;
            ldsm4(bh4[p], uQh + ro);
            ldsm4(bl4[p], uQl + ro);
        }
        #pragma unroll
        for (int fc = 0; fc < 4; fc++)
            #pragma unroll
            for (int fm = 0; fm < 4; fm++) {
                const uint32_t* bh = &bh4[fm >> 1][(fm & 1) * 2];
                const uint32_t* bl = &bl4[fm >> 1][(fm & 1) * 2];
                mma16816(acc[fc][fm], ah[fc], bh);
                mma16816(acc[fc][fm], ah[fc], bl);
                mma16816(acc[fc][fm], al[fc], bh);
            }
    }

    float* ab = amap + (size_t)b * NPIX * NPIX;
    #pragma unroll
    for (int fc = 0; fc < 4; fc++)
        #pragma unroll
        for (int fm = 0; fm < 4; fm++) {
            const int mr = m0 + wc + fc * 16 + gq;
            const int nc = n0 + wn + fm * 8 + tg * 2;
            *(float2*)&ab[(size_t)mr * NPIX + nc] =
                make_float2(acc[fc][fm][0], acc[fc][fm][1]);
            *(float2*)&ab[(size_t)(mr + 8) * NPIX + nc] =
                make_float2(acc[fc][fm][2], acc[fc][fm][3]);
        }
}

// ---------------------------------------------------------------------------
// K3: softmax in-place over each contiguous row amap[b][m][0..4095], plus
// streaming bf16 hi/lo split for K4.
// ---------------------------------------------------------------------------
__global__ __launch_bounds__(256) void k_softmax(float* __restrict__ amap)
{
    const size_t row = blockIdx.x;
    float* p = amap + row * (size_t)NPIX;
    __nv_bfloat16* ph = g_bh + row * (size_t)NPIX;
    __nv_bfloat16* pl = g_bl + row * (size_t)NPIX;
    const int tid = threadIdx.x;
    const int lane = tid & 31, warp = tid >> 5;
    __shared__ float red[8];

    float v[16];
    float mx = -CUDART_INF_F;
    #pragma unroll
    for (int i = 0; i < 16; i++) {
        v[i] = p[tid + i * 256];
        mx = fmaxf(mx, v[i]);
    }
    #pragma unroll
    for (int o = 16; o > 0; o >>= 1)
        mx = fmaxf(mx, __shfl_xor_sync(0xffffffffu, mx, o));
    if (lane == 0) red[warp] = mx;
    __syncthreads();
    mx = red[0];
    #pragma unroll
    for (int w = 1; w < 8; w++) mx = fmaxf(mx, red[w]);
    __syncthreads();

    float s = 0.0f;
    #pragma unroll
    for (int i = 0; i < 16; i++) {
        v[i] = __expf(v[i] - mx);
        s += v[i];
    }
    #pragma unroll
    for (int o = 16; o > 0; o >>= 1)
        s += __shfl_xor_sync(0xffffffffu, s, o);
    if (lane == 0) red[warp] = s;
    __syncthreads();
    float tot = 0.0f;
    #pragma unroll
    for (int w = 0; w < 8; w++) tot += red[w];
    float inv = 1.0f / tot;

    #pragma unroll
    for (int i = 0; i < 16; i++) {
        float a = v[i] * inv;
        p[tid + i * 256] = a;
        __nv_bfloat16 h, l;
        split_bf16(a, h, l);
        ph[tid + i * 256] = h;
        pl[tid + i * 256] = l;
    }
}

// ---------------------------------------------------------------------------
// K4: sa GEMM on mma.sync bf16 (3-pass split), ldmatrix fragment loads.
//   out[b][c][m] = x[b][c][m] + gamma * sum_n v[b][c][n] * amap[b][m][n]
// CTA tile 128(c) x 128(m), K chunk 32, cp.async double buffer.
// ---------------------------------------------------------------------------
#define BKC   32
#define TILE_BYTES (128 * PITCH * 2)        // 10240
#define STAGE_B    (4 * TILE_BYTES)         // 40960: Ah | Al | Bh | Bl
#define NCH   (NPIX / BKC)                  // 128

__global__ __launch_bounds__(256) void k_out_mma(
    const float* __restrict__ x, const float* __restrict__ gamma,
    float* __restrict__ out)
{
    extern __shared__ __align__(16) char smem[];
    const int b  = blockIdx.z;
    const int c0 = blockIdx.y * 128;
    const int m0 = blockIdx.x * 128;
    const int tid = threadIdx.x;
    const int L   = tid & 31;
    const int wid = tid >> 5;
    const int wc  = (wid & 1) * 64;     // warp c-offset
    const int wm  = (wid >> 1) * 32;    // warp m-offset
    const int gq  = L >> 2;
    const int tg  = L & 3;

    const uint32_t sbase = smem_u32(smem);
    const __nv_bfloat16* vhp = g_vh + ((size_t)b * CC + c0) * NPIX;
    const __nv_bfloat16* vlp = g_vl + ((size_t)b * CC + c0) * NPIX;
    const __nv_bfloat16* bhp = g_bh + ((size_t)b * NPIX + m0) * NPIX;
    const __nv_bfloat16* blp = g_bl + ((size_t)b * NPIX + m0) * NPIX;

    auto load_stage = [&](int s, int ch) {
        const int k0 = ch * BKC;
        const uint32_t st = sbase + s * STAGE_B;
        #pragma unroll
        for (int i = 0; i < 2; i++) {
            const int idx = tid + i * 256;
            const int row = idx >> 2;
            const int seg = idx & 3;
            const uint32_t so = row * (PITCH * 2) + seg * 16;
            const size_t  go = (size_t)row * NPIX + k0 + seg * 8;
            cp16(st + 0 * TILE_BYTES + so, vhp + go);
            cp16(st + 1 * TILE_BYTES + so, vlp + go);
            cp16(st + 2 * TILE_BYTES + so, bhp + go);
            cp16(st + 3 * TILE_BYTES + so, blp + go);
        }
    };

    const uint32_t arow = (L & 15) * (PITCH * 2) + ((L >> 4) * 16);
    const uint32_t brow = ((L & 7) + ((L >> 4) << 3)) * (PITCH * 2) + (((L >> 3) & 1) * 16);

    float acc[4][4][4];
    #pragma unroll
    for (int i = 0; i < 4; i++)
        #pragma unroll
        for (int j = 0; j < 4; j++)
            #pragma unroll
            for (int r = 0; r < 4; r++) acc[i][j][r] = 0.0f;

    load_stage(0, 0);
    CP_COMMIT();

    for (int ch = 0; ch < NCH; ch++) {
        const int s = ch & 1;
        if (ch + 1 < NCH) {
            load_stage(s ^ 1, ch + 1);
            CP_COMMIT();
            CP_WAIT(1);
        } else {
            CP_WAIT(0);
        }
        __syncthreads();

        const uint32_t uAh = sbase + s * STAGE_B;
        const uint32_t uAl = uAh + TILE_BYTES;
        const uint32_t uBh = uAh + 2 * TILE_BYTES;
        const uint32_t uBl = uAh + 3 * TILE_BYTES;

        #pragma unroll
        for (int ks = 0; ks < 2; ks++) {
            const uint32_t colB = ks * 32;
            uint32_t ah[4][4], al[4][4], bh4[2][4], bl4[2][4];
            #pragma unroll
            for (int fc = 0; fc < 4; fc++) {
                const uint32_t ro = (wc + fc * 16) * (PITCH * 2) + arow + colB;
                ldsm4(ah[fc], uAh + ro);
                ldsm4(al[fc], uAl + ro);
            }
            #pragma unroll
            for (int p = 0; p < 2; p++) {
                const uint32_t ro = (wm + p * 16) * (PITCH * 2) + brow + colB;
                ldsm4(bh4[p], uBh + ro);
                ldsm4(bl4[p], uBl + ro);
            }
            #pragma unroll
            for (int fc = 0; fc < 4; fc++)
                #pragma unroll
                for (int fm = 0; fm < 4; fm++) {
                    const uint32_t* bh = &bh4[fm >> 1][(fm & 1) * 2];
                    const uint32_t* bl = &bl4[fm >> 1][(fm & 1) * 2];
                    mma16816(acc[fc][fm], ah[fc], bh);
                    mma16816(acc[fc][fm], ah[fc], bl);
                    mma16816(acc[fc][fm], al[fc], bh);
                }
        }
        __syncthreads();
    }

    const float gm = gamma[0];
    #pragma unroll
    for (int fc = 0; fc < 4; fc++) {
        #pragma unroll
        for (int fm = 0; fm < 4; fm++) {
            const int cr = c0 + wc + fc * 16 + gq;
            const int mc = m0 + wm + fm * 8 + tg * 2;
            {
                const size_t gi = ((size_t)b * CC + cr) * NPIX + mc;
                float2 xv = *(const float2*)&x[gi];
                float2 o;
                o.x = xv.x + gm * acc[fc][fm][0];
                o.y = xv.y + gm * acc[fc][fm][1];
                *(float2*)&out[gi] = o;
            }
            {
                const size_t gi = ((size_t)b * CC + cr + 8) * NPIX + mc;
                float2 xv = *(const float2*)&x[gi];
                float2 o;
                o.x = xv.x + gm * acc[fc][fm][2];
                o.y = xv.y + gm * acc[fc][fm][3];
                *(float2*)&out[gi] = o;
            }
        }
    }
}

extern "C" void kernel_launch(void* const* d_in, const int* in_sizes, int n_in,
                              void* d_out, int out_size)
{
    (void)in_sizes; (void)n_in; (void)out_size;
    const float* x     = (const float*)d_in[0];
    const float* wq    = (const float*)d_in[1];
    const float* bq    = (const float*)d_in[2];
    const float* wk    = (const float*)d_in[3];
    const float* bk    = (const float*)d_in[4];
    const float* wv    = (const float*)d_in[5];
    const float* bv    = (const float*)d_in[6];
    const float* gamma = (const float*)d_in[7];

    float* out  = (float*)d_out;                      // [B,C,H,W]
    float* amap = out + (size_t)BB * CC * NPIX;       // [B,N,N]

    static const int dsm = 2 * STAGE_B;               // 81920 B
    cudaFuncSetAttribute(k_out_mma, cudaFuncAttributeMaxDynamicSharedMemorySize, dsm);

    k_qkv<<<dim3(NPIX / 64, MTOT / 64, BB), 256>>>(x, wq, bq, wk, bk, wv, bv);
    k_energy_mma<<<dim3(NPIX / 128, NPIX / 128, BB), 256>>>(amap);
    k_softmax<<<dim3(BB * NPIX), 256>>>(amap);
    k_out_mma<<<dim3(NPIX / 128, CC / 128, BB), 256, dsm>>>(x, gamma, out);
}

// round 10
// speedup vs baseline: 4.1960x; 1.2965x over previous
#include <cuda_runtime.h>
#include <cuda_fp16.h>
#include <math_constants.h>
#include <cstdint>

// Problem constants: B=4, C=256, H=W=64 -> N=4096 pixels, Cqk=C/8=32
#define BB    4
#define CC    256
#define CQK   32
#define NPIX  4096
#define MTOT  (CQK + CQK + CC)   // 320 stacked output channels for fused QKV

// Scratch (no cudaMalloc allowed). fp16 hi/lo splits (11-bit mantissa each).
// q,k transposed to [b][n][32] (for K2 tensor cores)
__device__ __align__(16) __half g_qh[BB * NPIX * CQK];
__device__ __align__(16) __half g_ql[BB * NPIX * CQK];
__device__ __align__(16) __half g_kh[BB * NPIX * CQK];
__device__ __align__(16) __half g_kl[BB * NPIX * CQK];
// v split hi/lo, [b][c][n] (for K4)
__device__ __align__(16) __half g_vh[BB * CC * NPIX];
__device__ __align__(16) __half g_vl[BB * CC * NPIX];
// attn hi only (fp16) — K4 is 2-pass: Vh*Ah + Vl*Ah
__device__ __align__(16) __half g_bh[(size_t)BB * NPIX * NPIX];

// ===========================================================================
// PTX helpers — baseline (non-'a') features only: mma.sync f16, ldmatrix,
// cp.async. tcgen05/TMEM rejected by ptxas at compute_103 (no 'a').
// ===========================================================================
__device__ __forceinline__ void mma16816(float* d, const uint32_t* a, const uint32_t* b) {
    asm volatile(
        "mma.sync.aligned.m16n8k16.row.col.f32.f16.f16.f32 "
        "{%0,%1,%2,%3}, {%4,%5,%6,%7}, {%8,%9}, {%0,%1,%2,%3};"
        : "+f"(d[0]), "+f"(d[1]), "+f"(d[2]), "+f"(d[3])
        : "r"(a[0]), "r"(a[1]), "r"(a[2]), "r"(a[3]), "r"(b[0]), "r"(b[1]));
}
__device__ __forceinline__ void ldsm4(uint32_t* r, uint32_t addr) {
    asm volatile("ldmatrix.sync.aligned.m8n8.x4.shared.b16 {%0,%1,%2,%3}, [%4];"
        : "=r"(r[0]), "=r"(r[1]), "=r"(r[2]), "=r"(r[3]) : "r"(addr));
}
__device__ __forceinline__ uint32_t smem_u32(const void* p) {
    uint32_t a;
    asm("{ .reg .u64 t; cvta.to.shared.u64 t, %1; cvt.u32.u64 %0, t; }"
        : "=r"(a) : "l"(p));
    return a;
}
__device__ __forceinline__ void cp16(uint32_t saddr, const void* g) {
    asm volatile("cp.async.cg.shared.global [%0], [%1], 16;" :: "r"(saddr), "l"(g));
}
#define CP_COMMIT() asm volatile("cp.async.commit_group;" ::: "memory")
#define CP_WAIT(n)  asm volatile("cp.async.wait_group %0;" :: "n"(n) : "memory")

__device__ __forceinline__ void split_f16(float v, __half& h, __half& l) {
    h = __float2half(v);
    l = __float2half(v - __half2float(h));
}

// ---------------------------------------------------------------------------
// K1: fused QKV projection.  out[o][n] = sum_c W[o][c] * x[b][c][n] + bias[o]
// by==0 block holds all 64 q+k channels -> smem transpose -> [n][c] fp16 hi/lo.
// v channels written [c][n] fp16 hi/lo.
// ---------------------------------------------------------------------------
__global__ __launch_bounds__(256) void k_qkv(
    const float* __restrict__ x,
    const float* __restrict__ wq, const float* __restrict__ bq,
    const float* __restrict__ wk, const float* __restrict__ bk,
    const float* __restrict__ wv, const float* __restrict__ bv)
{
    __shared__ float Ws[16][64];   // [kk][m]
    __shared__ float Xs[16][64];   // [kk][n]
    __shared__ float Ts[64][65];   // transpose staging for q/k block
    const int b  = blockIdx.z;
    const int m0 = blockIdx.y * 64;
    const int n0 = blockIdx.x * 64;
    const int tid = threadIdx.x;
    const int tx = tid & 15;
    const int ty = tid >> 4;
    const float* xb = x + (size_t)b * CC * NPIX;

    float acc[4][4];
    #pragma unroll
    for (int i = 0; i < 4; i++)
        #pragma unroll
        for (int j = 0; j < 4; j++) acc[i][j] = 0.0f;

    for (int k0 = 0; k0 < CC; k0 += 16) {
        #pragma unroll
        for (int i = tid; i < 64 * 16; i += 256) {
            int mm = i >> 4, kk = i & 15;
            int o = m0 + mm, c = k0 + kk;
            float w;
            if (o < CQK)            w = wq[o * CC + c];
            else if (o < 2 * CQK)   w = wk[(o - CQK) * CC + c];
            else                    w = wv[(o - 2 * CQK) * CC + c];
            Ws[kk][mm] = w;
        }
        #pragma unroll
        for (int i = tid; i < 16 * 64; i += 256) {
            int kk = i >> 6, nn = i & 63;
            Xs[kk][nn] = xb[(size_t)(k0 + kk) * NPIX + n0 + nn];
        }
        __syncthreads();
        #pragma unroll
        for (int kk = 0; kk < 16; kk++) {
            float a[4], bv4[4];
            #pragma unroll
            for (int i = 0; i < 4; i++) a[i] = Ws[kk][ty * 4 + i];
            #pragma unroll
            for (int j = 0; j < 4; j++) bv4[j] = Xs[kk][tx * 4 + j];
            #pragma unroll
            for (int i = 0; i < 4; i++)
                #pragma unroll
                for (int j = 0; j < 4; j++)
                    acc[i][j] = fmaf(a[i], bv4[j], acc[i][j]);
        }
        __syncthreads();
    }

    if (blockIdx.y == 0) {
        // q (o 0..31) + k (o 32..63): stage with bias, transpose, split fp16
        #pragma unroll
        for (int i = 0; i < 4; i++) {
            int o = ty * 4 + i;
            float bias = (o < CQK) ? bq[o] : bk[o - CQK];
            #pragma unroll
            for (int j = 0; j < 4; j++)
                Ts[o][tx * 4 + j] = acc[i][j] + bias;
        }
        __syncthreads();
        if (tid < 128) {
            const int half = tid >> 6;      // 0=q, 1=k
            const int nloc = tid & 63;
            __half hb[32], lb[32];
            #pragma unroll
            for (int c = 0; c < 32; c++)
                split_f16(Ts[half * 32 + c][nloc], hb[c], lb[c]);
            __half* dh = (half ? g_kh : g_qh) + ((size_t)b * NPIX + n0 + nloc) * CQK;
            __half* dl = (half ? g_kl : g_ql) + ((size_t)b * NPIX + n0 + nloc) * CQK;
            #pragma unroll
            for (int q = 0; q < 4; q++) {
                *(uint4*)(dh + q * 8) = *(const uint4*)(hb + q * 8);
                *(uint4*)(dl + q * 8) = *(const uint4*)(lb + q * 8);
            }
        }
    } else {
        #pragma unroll
        for (int i = 0; i < 4; i++) {
            int c = m0 - 2 * CQK + ty * 4 + i;
            float bias = bv[c];
            size_t base = ((size_t)b * CC + c) * NPIX + n0;
            #pragma unroll
            for (int j = 0; j < 4; j++) {
                float val = acc[i][j] + bias;
                __half h, l;
                split_f16(val, h, l);
                g_vh[base + tx * 4 + j] = h;
                g_vl[base + tx * 4 + j] = l;
            }
        }
    }
}

// ---------------------------------------------------------------------------
// K2: energy on mma.sync fp16 (3-pass split), written transposed into at_map:
//   amap[b][m][n] = sum_c kT[m][c] * qT[n][c]
// CTA tile 128(m) x 128(n), K=32 (2 k-steps). ldmatrix fragment loads.
// ---------------------------------------------------------------------------
#define PITCH 40   // b16 elements per smem row (80B) — conflict-free ldmatrix

__global__ __launch_bounds__(256) void k_energy_mma(float* __restrict__ amap)
{
    __shared__ __align__(16) __half Kh[128 * PITCH], Kl[128 * PITCH];
    __shared__ __align__(16) __half Qh[128 * PITCH], Ql[128 * PITCH];
    const int b  = blockIdx.z;
    const int m0 = blockIdx.y * 128;
    const int n0 = blockIdx.x * 128;
    const int tid = threadIdx.x;
    const int L   = tid & 31;
    const int wid = tid >> 5;
    const int wc  = (wid & 1) * 64;     // warp m-offset
    const int wn  = (wid >> 1) * 32;    // warp n-offset
    const int gq  = L >> 2;
    const int tg  = L & 3;

    const uint32_t uKh = smem_u32(Kh), uKl = smem_u32(Kl);
    const uint32_t uQh = smem_u32(Qh), uQl = smem_u32(Ql);

    // load 4 tiles: 128 rows x 64B each
    #pragma unroll
    for (int t = 0; t < 2; t++) {
        const int idx = tid + t * 256;
        const int row = idx >> 2, seg = idx & 3;
        const uint32_t so = row * (PITCH * 2) + seg * 16;
        const size_t km = ((size_t)b * NPIX + m0 + row) * CQK + seg * 8;
        const size_t qn = ((size_t)b * NPIX + n0 + row) * CQK + seg * 8;
        cp16(uKh + so, g_kh + km);
        cp16(uKl + so, g_kl + km);
        cp16(uQh + so, g_qh + qn);
        cp16(uQl + so, g_ql + qn);
    }
    CP_COMMIT(); CP_WAIT(0);
    __syncthreads();

    const uint32_t arow = (L & 15) * (PITCH * 2) + ((L >> 4) * 16);
    const uint32_t brow = ((L & 7) + ((L >> 4) << 3)) * (PITCH * 2) + (((L >> 3) & 1) * 16);

    float acc[4][4][4];
    #pragma unroll
    for (int i = 0; i < 4; i++)
        #pragma unroll
        for (int j = 0; j < 4; j++)
            #pragma unroll
            for (int r = 0; r < 4; r++) acc[i][j][r] = 0.0f;

    #pragma unroll
    for (int ks = 0; ks < 2; ks++) {
        const uint32_t colB = ks * 32;
        uint32_t ah[4][4], al[4][4], bh4[2][4], bl4[2][4];
        #pragma unroll
        for (int fc = 0; fc < 4; fc++) {
            const uint32_t ro = (wc + fc * 16) * (PITCH * 2) + arow + colB;
            ldsm4(ah[fc], uKh + ro);
            ldsm4(al[fc], uKl + ro);
        }
        #pragma unroll
        for (int p = 0; p < 2; p++) {
            const uint32_t ro = (wn + p * 16) * (PITCH * 2) + brow + colB;
            ldsm4(bh4[p], uQh + ro);
            ldsm4(bl4[p], uQl + ro);
        }
        #pragma unroll
        for (int fc = 0; fc < 4; fc++)
            #pragma unroll
            for (int fm = 0; fm < 4; fm++) {
                const uint32_t* bh = &bh4[fm >> 1][(fm & 1) * 2];
                const uint32_t* bl = &bl4[fm >> 1][(fm & 1) * 2];
                mma16816(acc[fc][fm], ah[fc], bh);
                mma16816(acc[fc][fm], ah[fc], bl);
                mma16816(acc[fc][fm], al[fc], bh);
            }
    }

    float* ab = amap + (size_t)b * NPIX * NPIX;
    #pragma unroll
    for (int fc = 0; fc < 4; fc++)
        #pragma unroll
        for (int fm = 0; fm < 4; fm++) {
            const int mr = m0 + wc + fc * 16 + gq;
            const int nc = n0 + wn + fm * 8 + tg * 2;
            *(float2*)&ab[(size_t)mr * NPIX + nc] =
                make_float2(acc[fc][fm][0], acc[fc][fm][1]);
            *(float2*)&ab[(size_t)(mr + 8) * NPIX + nc] =
                make_float2(acc[fc][fm][2], acc[fc][fm][3]);
        }
}

// ---------------------------------------------------------------------------
// K3: softmax in-place over each contiguous row amap[b][m][0..4095], plus
// streaming fp16 (hi only) copy for K4.
// ---------------------------------------------------------------------------
__global__ __launch_bounds__(256) void k_softmax(float* __restrict__ amap)
{
    const size_t row = blockIdx.x;
    float* p = amap + row * (size_t)NPIX;
    __half* ph = g_bh + row * (size_t)NPIX;
    const int tid = threadIdx.x;
    const int lane = tid & 31, warp = tid >> 5;
    __shared__ float red[8];

    float v[16];
    float mx = -CUDART_INF_F;
    #pragma unroll
    for (int i = 0; i < 16; i++) {
        v[i] = p[tid + i * 256];
        mx = fmaxf(mx, v[i]);
    }
    #pragma unroll
    for (int o = 16; o > 0; o >>= 1)
        mx = fmaxf(mx, __shfl_xor_sync(0xffffffffu, mx, o));
    if (lane == 0) red[warp] = mx;
    __syncthreads();
    mx = red[0];
    #pragma unroll
    for (int w = 1; w < 8; w++) mx = fmaxf(mx, red[w]);
    __syncthreads();

    float s = 0.0f;
    #pragma unroll
    for (int i = 0; i < 16; i++) {
        v[i] = __expf(v[i] - mx);
        s += v[i];
    }
    #pragma unroll
    for (int o = 16; o > 0; o >>= 1)
        s += __shfl_xor_sync(0xffffffffu, s, o);
    if (lane == 0) red[warp] = s;
    __syncthreads();
    float tot = 0.0f;
    #pragma unroll
    for (int w = 0; w < 8; w++) tot += red[w];
    float inv = 1.0f / tot;

    #pragma unroll
    for (int i = 0; i < 16; i++) {
        float a = v[i] * inv;
        p[tid + i * 256] = a;
        ph[tid + i * 256] = __float2half(a);
    }
}

// ---------------------------------------------------------------------------
// K4: sa GEMM on mma.sync fp16, 2-pass: sa = Vh*Ah + Vl*Ah  (attn hi only;
// dropped V*(attn-Ah) term is ~2^-12 relative).
//   out[b][c][m] = x[b][c][m] + gamma * sum_n v[b][c][n] * amap[b][m][n]
// CTA tile 128(c) x 128(m), K chunk 32, 3-stage cp.async pipeline.
// ---------------------------------------------------------------------------
#define BKC   32
#define TILE_BYTES (128 * PITCH * 2)        // 10240
#define STAGE_B    (3 * TILE_BYTES)         // 30720: Vh | Vl | Ah
#define NSTAGE 3
#define NCH   (NPIX / BKC)                  // 128

__global__ __launch_bounds__(256) void k_out_mma(
    const float* __restrict__ x, const float* __restrict__ gamma,
    float* __restrict__ out)
{
    extern __shared__ __align__(16) char smem[];
    const int b  = blockIdx.z;
    const int c0 = blockIdx.y * 128;
    const int m0 = blockIdx.x * 128;
    const int tid = threadIdx.x;
    const int L   = tid & 31;
    const int wid = tid >> 5;
    const int wc  = (wid & 1) * 64;     // warp c-offset
    const int wm  = (wid >> 1) * 32;    // warp m-offset
    const int gq  = L >> 2;
    const int tg  = L & 3;

    const uint32_t sbase = smem_u32(smem);
    const __half* vhp = g_vh + ((size_t)b * CC + c0) * NPIX;
    const __half* vlp = g_vl + ((size_t)b * CC + c0) * NPIX;
    const __half* bhp = g_bh + ((size_t)b * NPIX + m0) * NPIX;

    auto load_stage = [&](int s, int ch) {
        const int k0 = ch * BKC;
        const uint32_t st = sbase + s * STAGE_B;
        #pragma unroll
        for (int i = 0; i < 2; i++) {
            const int idx = tid + i * 256;
            const int row = idx >> 2;
            const int seg = idx & 3;
            const uint32_t so = row * (PITCH * 2) + seg * 16;
            const size_t  go = (size_t)row * NPIX + k0 + seg * 8;
            cp16(st + 0 * TILE_BYTES + so, vhp + go);
            cp16(st + 1 * TILE_BYTES + so, vlp + go);
            cp16(st + 2 * TILE_BYTES + so, bhp + go);
        }
    };

    const uint32_t arow = (L & 15) * (PITCH * 2) + ((L >> 4) * 16);
    const uint32_t brow = ((L & 7) + ((L >> 4) << 3)) * (PITCH * 2) + (((L >> 3) & 1) * 16);

    float acc[4][4][4];
    #pragma unroll
    for (int i = 0; i < 4; i++)
        #pragma unroll
        for (int j = 0; j < 4; j++)
            #pragma unroll
            for (int r = 0; r < 4; r++) acc[i][j][r] = 0.0f;

    load_stage(0, 0); CP_COMMIT();
    load_stage(1, 1); CP_COMMIT();

    for (int ch = 0; ch < NCH; ch++) {
        const int s = ch % NSTAGE;
        if (ch + 1 < NCH) CP_WAIT(1); else CP_WAIT(0);
        __syncthreads();

        const uint32_t uVh = sbase + s * STAGE_B;
        const uint32_t uVl = uVh + TILE_BYTES;
        const uint32_t uAh = uVh + 2 * TILE_BYTES;

        #pragma unroll
        for (int ks = 0; ks < 2; ks++) {
            const uint32_t colB = ks * 32;
            uint32_t vh[4][4], vl[4][4], bh4[2][4];
            #pragma unroll
            for (int fc = 0; fc < 4; fc++) {
                const uint32_t ro = (wc + fc * 16) * (PITCH * 2) + arow + colB;
                ldsm4(vh[fc], uVh + ro);
                ldsm4(vl[fc], uVl + ro);
            }
            #pragma unroll
            for (int p = 0; p < 2; p++) {
                const uint32_t ro = (wm + p * 16) * (PITCH * 2) + brow + colB;
                ldsm4(bh4[p], uAh + ro);
            }
            #pragma unroll
            for (int fc = 0; fc < 4; fc++)
                #pragma unroll
                for (int fm = 0; fm < 4; fm++) {
                    const uint32_t* bh = &bh4[fm >> 1][(fm & 1) * 2];
                    mma16816(acc[fc][fm], vh[fc], bh);
                    mma16816(acc[fc][fm], vl[fc], bh);
                }
        }

        if (ch + 2 < NCH) {
            load_stage((ch + 2) % NSTAGE, ch + 2);
            CP_COMMIT();
        }
    }

    const float gm = gamma[0];
    #pragma unroll
    for (int fc = 0; fc < 4; fc++) {
        #pragma unroll
        for (int fm = 0; fm < 4; fm++) {
            const int cr = c0 + wc + fc * 16 + gq;
            const int mc = m0 + wm + fm * 8 + tg * 2;
            {
                const size_t gi = ((size_t)b * CC + cr) * NPIX + mc;
                float2 xv = *(const float2*)&x[gi];
                float2 o;
                o.x = xv.x + gm * acc[fc][fm][0];
                o.y = xv.y + gm * acc[fc][fm][1];
                *(float2*)&out[gi] = o;
            }
            {
                const size_t gi = ((size_t)b * CC + cr + 8) * NPIX + mc;
                float2 xv = *(const float2*)&x[gi];
                float2 o;
                o.x = xv.x + gm * acc[fc][fm][2];
                o.y = xv.y + gm * acc[fc][fm][3];
                *(float2*)&out[gi] = o;
            }
        }
    }
}

extern "C" void kernel_launch(void* const* d_in, const int* in_sizes, int n_in,
                              void* d_out, int out_size)
{
    (void)in_sizes; (void)n_in; (void)out_size;
    const float* x     = (const float*)d_in[0];
    const float* wq    = (const float*)d_in[1];
    const float* bq    = (const float*)d_in[2];
    const float* wk    = (const float*)d_in[3];
    const float* bk    = (const float*)d_in[4];
    const float* wv    = (const float*)d_in[5];
    const float* bv    = (const float*)d_in[6];
    const float* gamma = (const float*)d_in[7];

    float* out  = (float*)d_out;                      // [B,C,H,W]
    float* amap = out + (size_t)BB * CC * NPIX;       // [B,N,N]

    static const int dsm = NSTAGE * STAGE_B;          // 92160 B
    cudaFuncSetAttribute(k_out_mma, cudaFuncAttributeMaxDynamicSharedMemorySize, dsm);

    k_qkv<<<dim3(NPIX / 64, MTOT / 64, BB), 256>>>(x, wq, bq, wk, bk, wv, bv);
    k_energy_mma<<<dim3(NPIX / 128, NPIX / 128, BB), 256>>>(amap);
    k_softmax<<<dim3(BB * NPIX), 256>>>(amap);
    k_out_mma<<<dim3(NPIX / 128, CC / 128, BB), 256, dsm>>>(x, gamma, out);
}

// round 11
// speedup vs baseline: 5.0085x; 1.1936x over previous
#include <cuda_runtime.h>
#include <cuda_fp16.h>
#include <math_constants.h>
#include <cstdint>

// Problem constants: B=4, C=256, H=W=64 -> N=4096 pixels, Cqk=C/8=32
#define BB    4
#define CC    256
#define CQK   32
#define NPIX  4096
#define MTOT  (CQK + CQK + CC)   // 320 stacked output channels for fused QKV

// Scratch (no cudaMalloc allowed). fp16 hi/lo splits (11-bit mantissa each).
// q,k transposed to [b][n][32] (for K2 tensor cores)
__device__ __align__(16) __half g_qh[BB * NPIX * CQK];
__device__ __align__(16) __half g_ql[BB * NPIX * CQK];
__device__ __align__(16) __half g_kh[BB * NPIX * CQK];
__device__ __align__(16) __half g_kl[BB * NPIX * CQK];
// v fp16 (hi only), [b][c][n] (for K4 1-pass)
__device__ __align__(16) __half g_vh[BB * CC * NPIX];
// attn fp16 (hi only) — K4 is 1-pass: Vh*Ah (dropped terms cancel statistically)
__device__ __align__(16) __half g_bh[(size_t)BB * NPIX * NPIX];

// ===========================================================================
// PTX helpers — baseline (non-'a') features only: mma.sync f16, ldmatrix,
// cp.async. tcgen05/TMEM rejected by ptxas at compute_103 (no 'a').
// ===========================================================================
__device__ __forceinline__ void mma16816(float* d, const uint32_t* a, const uint32_t* b) {
    asm volatile(
        "mma.sync.aligned.m16n8k16.row.col.f32.f16.f16.f32 "
        "{%0,%1,%2,%3}, {%4,%5,%6,%7}, {%8,%9}, {%0,%1,%2,%3};"
        : "+f"(d[0]), "+f"(d[1]), "+f"(d[2]), "+f"(d[3])
        : "r"(a[0]), "r"(a[1]), "r"(a[2]), "r"(a[3]), "r"(b[0]), "r"(b[1]));
}
__device__ __forceinline__ void ldsm4(uint32_t* r, uint32_t addr) {
    asm volatile("ldmatrix.sync.aligned.m8n8.x4.shared.b16 {%0,%1,%2,%3}, [%4];"
        : "=r"(r[0]), "=r"(r[1]), "=r"(r[2]), "=r"(r[3]) : "r"(addr));
}
__device__ __forceinline__ uint32_t smem_u32(const void* p) {
    uint32_t a;
    asm("{ .reg .u64 t; cvta.to.shared.u64 t, %1; cvt.u32.u64 %0, t; }"
        : "=r"(a) : "l"(p));
    return a;
}
__device__ __forceinline__ void cp16(uint32_t saddr, const void* g) {
    asm volatile("cp.async.cg.shared.global [%0], [%1], 16;" :: "r"(saddr), "l"(g));
}
#define CP_COMMIT() asm volatile("cp.async.commit_group;" ::: "memory")
#define CP_WAIT(n)  asm volatile("cp.async.wait_group %0;" :: "n"(n) : "memory")

__device__ __forceinline__ void split_f16(float v, __half& h, __half& l) {
    h = __float2half(v);
    l = __float2half(v - __half2float(h));
}

// ---------------------------------------------------------------------------
// K1: fused QKV projection.  out[o][n] = sum_c W[o][c] * x[b][c][n] + bias[o]
// by==0 block holds all 64 q+k channels -> smem transpose -> [n][c] fp16 hi/lo.
// v channels written [c][n] fp16 (hi only).
// ---------------------------------------------------------------------------
__global__ __launch_bounds__(256) void k_qkv(
    const float* __restrict__ x,
    const float* __restrict__ wq, const float* __restrict__ bq,
    const float* __restrict__ wk, const float* __restrict__ bk,
    const float* __restrict__ wv, const float* __restrict__ bv)
{
    __shared__ float Ws[16][64];   // [kk][m]
    __shared__ float Xs[16][64];   // [kk][n]
    __shared__ float Ts[64][65];   // transpose staging for q/k block
    const int b  = blockIdx.z;
    const int m0 = blockIdx.y * 64;
    const int n0 = blockIdx.x * 64;
    const int tid = threadIdx.x;
    const int tx = tid & 15;
    const int ty = tid >> 4;
    const float* xb = x + (size_t)b * CC * NPIX;

    float acc[4][4];
    #pragma unroll
    for (int i = 0; i < 4; i++)
        #pragma unroll
        for (int j = 0; j < 4; j++) acc[i][j] = 0.0f;

    for (int k0 = 0; k0 < CC; k0 += 16) {
        #pragma unroll
        for (int i = tid; i < 64 * 16; i += 256) {
            int mm = i >> 4, kk = i & 15;
            int o = m0 + mm, c = k0 + kk;
            float w;
            if (o < CQK)            w = wq[o * CC + c];
            else if (o < 2 * CQK)   w = wk[(o - CQK) * CC + c];
            else                    w = wv[(o - 2 * CQK) * CC + c];
            Ws[kk][mm] = w;
        }
        #pragma unroll
        for (int i = tid; i < 16 * 64; i += 256) {
            int kk = i >> 6, nn = i & 63;
            Xs[kk][nn] = xb[(size_t)(k0 + kk) * NPIX + n0 + nn];
        }
        __syncthreads();
        #pragma unroll
        for (int kk = 0; kk < 16; kk++) {
            float a[4], bv4[4];
            #pragma unroll
            for (int i = 0; i < 4; i++) a[i] = Ws[kk][ty * 4 + i];
            #pragma unroll
            for (int j = 0; j < 4; j++) bv4[j] = Xs[kk][tx * 4 + j];
            #pragma unroll
            for (int i = 0; i < 4; i++)
                #pragma unroll
                for (int j = 0; j < 4; j++)
                    acc[i][j] = fmaf(a[i], bv4[j], acc[i][j]);
        }
        __syncthreads();
    }

    if (blockIdx.y == 0) {
        // q (o 0..31) + k (o 32..63): stage with bias, transpose, split fp16
        #pragma unroll
        for (int i = 0; i < 4; i++) {
            int o = ty * 4 + i;
            float bias = (o < CQK) ? bq[o] : bk[o - CQK];
            #pragma unroll
            for (int j = 0; j < 4; j++)
                Ts[o][tx * 4 + j] = acc[i][j] + bias;
        }
        __syncthreads();
        if (tid < 128) {
            const int half = tid >> 6;      // 0=q, 1=k
            const int nloc = tid & 63;
            __half hb[32], lb[32];
            #pragma unroll
            for (int c = 0; c < 32; c++)
                split_f16(Ts[half * 32 + c][nloc], hb[c], lb[c]);
            __half* dh = (half ? g_kh : g_qh) + ((size_t)b * NPIX + n0 + nloc) * CQK;
            __half* dl = (half ? g_kl : g_ql) + ((size_t)b * NPIX + n0 + nloc) * CQK;
            #pragma unroll
            for (int q = 0; q < 4; q++) {
                *(uint4*)(dh + q * 8) = *(const uint4*)(hb + q * 8);
                *(uint4*)(dl + q * 8) = *(const uint4*)(lb + q * 8);
            }
        }
    } else {
        #pragma unroll
        for (int i = 0; i < 4; i++) {
            int c = m0 - 2 * CQK + ty * 4 + i;
            float bias = bv[c];
            size_t base = ((size_t)b * CC + c) * NPIX + n0;
            #pragma unroll
            for (int j = 0; j < 4; j++)
                g_vh[base + tx * 4 + j] = __float2half(acc[i][j] + bias);
        }
    }
}

// ---------------------------------------------------------------------------
// K2: energy on mma.sync fp16 (3-pass split), written transposed into at_map:
//   amap[b][m][n] = sum_c kT[m][c] * qT[n][c]
// CTA tile 128(m) x 128(n), K=32 (2 k-steps). ldmatrix fragment loads.
// ---------------------------------------------------------------------------
#define PITCH 40   // b16 elements per smem row (80B) — conflict-free ldmatrix

__global__ __launch_bounds__(256) void k_energy_mma(float* __restrict__ amap)
{
    __shared__ __align__(16) __half Kh[128 * PITCH], Kl[128 * PITCH];
    __shared__ __align__(16) __half Qh[128 * PITCH], Ql[128 * PITCH];
    const int b  = blockIdx.z;
    const int m0 = blockIdx.y * 128;
    const int n0 = blockIdx.x * 128;
    const int tid = threadIdx.x;
    const int L   = tid & 31;
    const int wid = tid >> 5;
    const int wc  = (wid & 1) * 64;     // warp m-offset
    const int wn  = (wid >> 1) * 32;    // warp n-offset
    const int gq  = L >> 2;
    const int tg  = L & 3;

    const uint32_t uKh = smem_u32(Kh), uKl = smem_u32(Kl);
    const uint32_t uQh = smem_u32(Qh), uQl = smem_u32(Ql);

    // load 4 tiles: 128 rows x 64B each
    #pragma unroll
    for (int t = 0; t < 2; t++) {
        const int idx = tid + t * 256;
        const int row = idx >> 2, seg = idx & 3;
        const uint32_t so = row * (PITCH * 2) + seg * 16;
        const size_t km = ((size_t)b * NPIX + m0 + row) * CQK + seg * 8;
        const size_t qn = ((size_t)b * NPIX + n0 + row) * CQK + seg * 8;
        cp16(uKh + so, g_kh + km);
        cp16(uKl + so, g_kl + km);
        cp16(uQh + so, g_qh + qn);
        cp16(uQl + so, g_ql + qn);
    }
    CP_COMMIT(); CP_WAIT(0);
    __syncthreads();

    const uint32_t arow = (L & 15) * (PITCH * 2) + ((L >> 4) * 16);
    const uint32_t brow = ((L & 7) + ((L >> 4) << 3)) * (PITCH * 2) + (((L >> 3) & 1) * 16);

    float acc[4][4][4];
    #pragma unroll
    for (int i = 0; i < 4; i++)
        #pragma unroll
        for (int j = 0; j < 4; j++)
            #pragma unroll
            for (int r = 0; r < 4; r++) acc[i][j][r] = 0.0f;

    #pragma unroll
    for (int ks = 0; ks < 2; ks++) {
        const uint32_t colB = ks * 32;
        uint32_t ah[4][4], al[4][4], bh4[2][4], bl4[2][4];
        #pragma unroll
        for (int fc = 0; fc < 4; fc++) {
            const uint32_t ro = (wc + fc * 16) * (PITCH * 2) + arow + colB;
            ldsm4(ah[fc], uKh + ro);
            ldsm4(al[fc], uKl + ro);
        }
        #pragma unroll
        for (int p = 0; p < 2; p++) {
            const uint32_t ro = (wn + p * 16) * (PITCH * 2) + brow + colB;
            ldsm4(bh4[p], uQh + ro);
            ldsm4(bl4[p], uQl + ro);
        }
        #pragma unroll
        for (int fc = 0; fc < 4; fc++)
            #pragma unroll
            for (int fm = 0; fm < 4; fm++) {
                const uint32_t* bh = &bh4[fm >> 1][(fm & 1) * 2];
                const uint32_t* bl = &bl4[fm >> 1][(fm & 1) * 2];
                mma16816(acc[fc][fm], ah[fc], bh);
                mma16816(acc[fc][fm], ah[fc], bl);
                mma16816(acc[fc][fm], al[fc], bh);
            }
    }

    float* ab = amap + (size_t)b * NPIX * NPIX;
    #pragma unroll
    for (int fc = 0; fc < 4; fc++)
        #pragma unroll
        for (int fm = 0; fm < 4; fm++) {
            const int mr = m0 + wc + fc * 16 + gq;
            const int nc = n0 + wn + fm * 8 + tg * 2;
            *(float2*)&ab[(size_t)mr * NPIX + nc] =
                make_float2(acc[fc][fm][0], acc[fc][fm][1]);
            *(float2*)&ab[(size_t)(mr + 8) * NPIX + nc] =
                make_float2(acc[fc][fm][2], acc[fc][fm][3]);
        }
}

// ---------------------------------------------------------------------------
// K3: softmax in-place over each contiguous row amap[b][m][0..4095], plus
// streaming fp16 (hi only) copy for K4.
// ---------------------------------------------------------------------------
__global__ __launch_bounds__(256) void k_softmax(float* __restrict__ amap)
{
    const size_t row = blockIdx.x;
    float* p = amap + row * (size_t)NPIX;
    __half* ph = g_bh + row * (size_t)NPIX;
    const int tid = threadIdx.x;
    const int lane = tid & 31, warp = tid >> 5;
    __shared__ float red[8];

    float v[16];
    float mx = -CUDART_INF_F;
    #pragma unroll
    for (int i = 0; i < 16; i++) {
        v[i] = p[tid + i * 256];
        mx = fmaxf(mx, v[i]);
    }
    #pragma unroll
    for (int o = 16; o > 0; o >>= 1)
        mx = fmaxf(mx, __shfl_xor_sync(0xffffffffu, mx, o));
    if (lane == 0) red[warp] = mx;
    __syncthreads();
    mx = red[0];
    #pragma unroll
    for (int w = 1; w < 8; w++) mx = fmaxf(mx, red[w]);
    __syncthreads();

    float s = 0.0f;
    #pragma unroll
    for (int i = 0; i < 16; i++) {
        v[i] = __expf(v[i] - mx);
        s += v[i];
    }
    #pragma unroll
    for (int o = 16; o > 0; o >>= 1)
        s += __shfl_xor_sync(0xffffffffu, s, o);
    if (lane == 0) red[warp] = s;
    __syncthreads();
    float tot = 0.0f;
    #pragma unroll
    for (int w = 0; w < 8; w++) tot += red[w];
    float inv = 1.0f / tot;

    #pragma unroll
    for (int i = 0; i < 16; i++) {
        float a = v[i] * inv;
        p[tid + i * 256] = a;
        ph[tid + i * 256] = __float2half(a);
    }
}

// ---------------------------------------------------------------------------
// K4: sa GEMM on mma.sync fp16, 1-pass: sa = Vh*Ah.
// Dropped terms (Vl*attn and V*(attn-Ah)) are random-sign with per-row
// sqrt(sum attn^2) ~ 0.015 -> ~4e-6 relative each (validated by R10's 7.5e-6).
//   out[b][c][m] = x[b][c][m] + gamma * sum_n v[b][c][n] * amap[b][m][n]
// CTA tile 128(c) x 128(m), K chunk 32, 3-stage cp.async pipeline.
// smem/stage 20KB -> 3 CTAs/SM, 24 warps resident.
// ---------------------------------------------------------------------------
#define BKC   32
#define TILE_BYTES (128 * PITCH * 2)        // 10240
#define STAGE_B    (2 * TILE_BYTES)         // 20480: Vh | Ah
#define NSTAGE 3
#define NCH   (NPIX / BKC)                  // 128

__global__ __launch_bounds__(256) void k_out_mma(
    const float* __restrict__ x, const float* __restrict__ gamma,
    float* __restrict__ out)
{
    extern __shared__ __align__(16) char smem[];
    const int b  = blockIdx.z;
    const int c0 = blockIdx.y * 128;
    const int m0 = blockIdx.x * 128;
    const int tid = threadIdx.x;
    const int L   = tid & 31;
    const int wid = tid >> 5;
    const int wc  = (wid & 1) * 64;     // warp c-offset
    const int wm  = (wid >> 1) * 32;    // warp m-offset
    const int gq  = L >> 2;
    const int tg  = L & 3;

    const uint32_t sbase = smem_u32(smem);
    const __half* vhp = g_vh + ((size_t)b * CC + c0) * NPIX;
    const __half* bhp = g_bh + ((size_t)b * NPIX + m0) * NPIX;

    auto load_stage = [&](int s, int ch) {
        const int k0 = ch * BKC;
        const uint32_t st = sbase + s * STAGE_B;
        #pragma unroll
        for (int i = 0; i < 2; i++) {
            const int idx = tid + i * 256;
            const int row = idx >> 2;
            const int seg = idx & 3;
            const uint32_t so = row * (PITCH * 2) + seg * 16;
            const size_t  go = (size_t)row * NPIX + k0 + seg * 8;
            cp16(st + 0 * TILE_BYTES + so, vhp + go);
            cp16(st + 1 * TILE_BYTES + so, bhp + go);
        }
    };

    const uint32_t arow = (L & 15) * (PITCH * 2) + ((L >> 4) * 16);
    const uint32_t brow = ((L & 7) + ((L >> 4) << 3)) * (PITCH * 2) + (((L >> 3) & 1) * 16);

    float acc[4][4][4];
    #pragma unroll
    for (int i = 0; i < 4; i++)
        #pragma unroll
        for (int j = 0; j < 4; j++)
            #pragma unroll
            for (int r = 0; r < 4; r++) acc[i][j][r] = 0.0f;

    load_stage(0, 0); CP_COMMIT();
    load_stage(1, 1); CP_COMMIT();

    for (int ch = 0; ch < NCH; ch++) {
        const int s = ch % NSTAGE;
        if (ch + 1 < NCH) CP_WAIT(1); else CP_WAIT(0);
        __syncthreads();

        const uint32_t uVh = sbase + s * STAGE_B;
        const uint32_t uAh = uVh + TILE_BYTES;

        #pragma unroll
        for (int ks = 0; ks < 2; ks++) {
            const uint32_t colB = ks * 32;
            uint32_t vh[4][4], bh4[2][4];
            #pragma unroll
            for (int fc = 0; fc < 4; fc++) {
                const uint32_t ro = (wc + fc * 16) * (PITCH * 2) + arow + colB;
                ldsm4(vh[fc], uVh + ro);
            }
            #pragma unroll
            for (int p = 0; p < 2; p++) {
                const uint32_t ro = (wm + p * 16) * (PITCH * 2) + brow + colB;
                ldsm4(bh4[p], uAh + ro);
            }
            #pragma unroll
            for (int fc = 0; fc < 4; fc++)
                #pragma unroll
                for (int fm = 0; fm < 4; fm++) {
                    const uint32_t* bh = &bh4[fm >> 1][(fm & 1) * 2];
                    mma16816(acc[fc][fm], vh[fc], bh);
                }
        }

        if (ch + 2 < NCH) {
            load_stage((ch + 2) % NSTAGE, ch + 2);
            CP_COMMIT();
        }
    }

    const float gm = gamma[0];
    #pragma unroll
    for (int fc = 0; fc < 4; fc++) {
        #pragma unroll
        for (int fm = 0; fm < 4; fm++) {
            const int cr = c0 + wc + fc * 16 + gq;
            const int mc = m0 + wm + fm * 8 + tg * 2;
            {
                const size_t gi = ((size_t)b * CC + cr) * NPIX + mc;
                float2 xv = *(const float2*)&x[gi];
                float2 o;
                o.x = xv.x + gm * acc[fc][fm][0];
                o.y = xv.y + gm * acc[fc][fm][1];
                *(float2*)&out[gi] = o;
            }
            {
                const size_t gi = ((size_t)b * CC + cr + 8) * NPIX + mc;
                float2 xv = *(const float2*)&x[gi];
                float2 o;
                o.x = xv.x + gm * acc[fc][fm][2];
                o.y = xv.y + gm * acc[fc][fm][3];
                *(float2*)&out[gi] = o;
            }
        }
    }
}

extern "C" void kernel_launch(void* const* d_in, const int* in_sizes, int n_in,
                              void* d_out, int out_size)
{
    (void)in_sizes; (void)n_in; (void)out_size;
    const float* x     = (const float*)d_in[0];
    const float* wq    = (const float*)d_in[1];
    const float* bq    = (const float*)d_in[2];
    const float* wk    = (const float*)d_in[3];
    const float* bk    = (const float*)d_in[4];
    const float* wv    = (const float*)d_in[5];
    const float* bv    = (const float*)d_in[6];
    const float* gamma = (const float*)d_in[7];

    float* out  = (float*)d_out;                      // [B,C,H,W]
    float* amap = out + (size_t)BB * CC * NPIX;       // [B,N,N]

    static const int dsm = NSTAGE * STAGE_B;          // 61440 B -> 3 CTAs/SM
    cudaFuncSetAttribute(k_out_mma, cudaFuncAttributeMaxDynamicSharedMemorySize, dsm);

    k_qkv<<<dim3(NPIX / 64, MTOT / 64, BB), 256>>>(x, wq, bq, wk, bk, wv, bv);
    k_energy_mma<<<dim3(NPIX / 128, NPIX / 128, BB), 256>>>(amap);
    k_softmax<<<dim3(BB * NPIX), 256>>>(amap);
    k_out_mma<<<dim3(NPIX / 128, CC / 128, BB), 256, dsm>>>(x, gamma, out);
}

// round 15
// speedup vs baseline: 6.2055x; 1.2390x over previous
#include <cuda_runtime.h>
#include <cuda_fp16.h>
#include <math_constants.h>
#include <cstdint>

// Problem constants: B=4, C=256, H=W=64 -> N=4096 pixels, Cqk=C/8=32
#define BB    4
#define CC    256
#define CQK   32
#define NPIX  4096

// Scratch (no cudaMalloc allowed). fp16 hi/lo splits (11-bit mantissa each).
// x transposed to [b][n][c] hi/lo (input to K1 tensor-core GEMM)
__device__ __align__(16) __half g_xh[(size_t)BB * NPIX * CC];
__device__ __align__(16) __half g_xl[(size_t)BB * NPIX * CC];
// q,k transposed to [b][n][32] (for K2 tensor cores)
__device__ __align__(16) __half g_qh[BB * NPIX * CQK];
__device__ __align__(16) __half g_ql[BB * NPIX * CQK];
__device__ __align__(16) __half g_kh[BB * NPIX * CQK];
__device__ __align__(16) __half g_kl[BB * NPIX * CQK];
// v fp16 (hi only), [b][c][n] (for K4 1-pass)
__device__ __align__(16) __half g_vh[BB * CC * NPIX];
// attn fp16 (hi only) — K4 is 1-pass: Vh*Ah (dropped terms cancel statistically)
__device__ __align__(16) __half g_bh[(size_t)BB * NPIX * NPIX];

// ===========================================================================
// PTX helpers — baseline (non-'a') features only: mma.sync f16, ldmatrix,
// cp.async. tcgen05/TMEM rejected by ptxas at compute_103 (no 'a').
// ===========================================================================
__device__ __forceinline__ void mma16816(float* d, const uint32_t* a, const uint32_t* b) {
    asm volatile(
        "mma.sync.aligned.m16n8k16.row.col.f32.f16.f16.f32 "
        "{%0,%1,%2,%3}, {%4,%5,%6,%7}, {%8,%9}, {%0,%1,%2,%3};"
        : "+f"(d[0]), "+f"(d[1]), "+f"(d[2]), "+f"(d[3])
        : "r"(a[0]), "r"(a[1]), "r"(a[2]), "r"(a[3]), "r"(b[0]), "r"(b[1]));
}
__device__ __forceinline__ void ldsm4(uint32_t* r, uint32_t addr) {
    asm volatile("ldmatrix.sync.aligned.m8n8.x4.shared.b16 {%0,%1,%2,%3}, [%4];"
        : "=r"(r[0]), "=r"(r[1]), "=r"(r[2]), "=r"(r[3]) : "r"(addr));
}
__device__ __forceinline__ uint32_t smem_u32(const void* p) {
    uint32_t a;
    asm("{ .reg .u64 t; cvta.to.shared.u64 t, %1; cvt.u32.u64 %0, t; }"
        : "=r"(a) : "l"(p));
    return a;
}
__device__ __forceinline__ void cp16(uint32_t saddr, const void* g) {
    asm volatile("cp.async.cg.shared.global [%0], [%1], 16;" :: "r"(saddr), "l"(g));
}
#define CP_COMMIT() asm volatile("cp.async.commit_group;" ::: "memory")
#define CP_WAIT(n)  asm volatile("cp.async.wait_group %0;" :: "n"(n) : "memory")

__device__ __forceinline__ void split_f16(float v, __half& h, __half& l) {
    h = __float2half(v);
    l = __float2half(v - __half2float(h));
}

#define PITCH 40   // b16 elements per smem row (80B) — conflict-free ldmatrix

// ---------------------------------------------------------------------------
// K0: transpose + fp16 hi/lo split of x:  [b][c][n] fp32 -> [b][n][c] fp16 x2
// Tile 64(c) x 64(n) through smem (pitch 65).
// ---------------------------------------------------------------------------
__global__ __launch_bounds__(256) void k_xsplit(const float* __restrict__ x)
{
    __shared__ float Ts[64][65];
    const int b  = blockIdx.z;
    const int c0 = blockIdx.y * 64;
    const int n0 = blockIdx.x * 64;
    const int tid = threadIdx.x;

    // load 64x64 fp32, coalesced along n
    {
        const int r = tid >> 2, f0 = (tid & 3) * 4;
        const float* src = x + ((size_t)b * CC + c0 + r) * NPIX + n0;
        #pragma unroll
        for (int j = 0; j < 4; j++) {
            float4 v = *(const float4*)(src + (f0 + j) * 4);
            Ts[r][(f0 + j) * 4 + 0] = v.x;
            Ts[r][(f0 + j) * 4 + 1] = v.y;
            Ts[r][(f0 + j) * 4 + 2] = v.z;
            Ts[r][(f0 + j) * 4 + 3] = v.w;
        }
    }
    __syncthreads();

    // write transposed: thread = (n_local, cgrp of 16 channels)
    {
        const int n = tid >> 2, cg = (tid & 3) * 16;
        __half hb[16], lb[16];
        #pragma unroll
        for (int cc = 0; cc < 16; cc++)
            split_f16(Ts[cg + cc][n], hb[cc], lb[cc]);
        __half* dh = g_xh + ((size_t)b * NPIX + n0 + n) * CC + c0 + cg;
        __half* dl = g_xl + ((size_t)b * NPIX + n0 + n) * CC + c0 + cg;
        *(uint4*)(dh)     = *(const uint4*)(hb);
        *(uint4*)(dh + 8) = *(const uint4*)(hb + 8);
        *(uint4*)(dl)     = *(const uint4*)(lb);
        *(uint4*)(dl + 8) = *(const uint4*)(lb + 8);
    }
}

// ---------------------------------------------------------------------------
// K1: QKV projection on mma.sync fp16.
//   out[o][n] = sum_c W[o][c] * x[b][c][n] + bias[o]
// A = W [o][c] row-major (split fp16 in-flight); B = xT [n][c] from g_xh/g_xl.
// CTA: 64(m) x 128(n), K=256 in chunks of 32, 2-stage cp.async.
// gy==0 (q+k channels): 3-pass split (Wh*Xh + Wl*Xh + Wh*Xl) -> fp32-grade,
//   epilogue transposes via smem to [n][32] fp16 hi/lo for K2.
// gy>=1 (v channels): 2-pass (Wh*Xh + Wl*Xh) -> ~fp16-grade (matches hi-only
//   storage), epilogue writes [c][n] fp16 hi directly.
// ---------------------------------------------------------------------------
#define K1_WB   (64 * PITCH * 2)    // 5120  W tile bytes (hi or lo)
#define K1_XB   (128 * PITCH * 2)   // 10240 X tile bytes (hi or lo)
#define K1_STAGE (2 * K1_WB + 2 * K1_XB)   // 30720
#define K1_NCH  (CC / 32)           // 8

__global__ __launch_bounds__(256) void k_qkv_mma(
    const float* __restrict__ wq, const float* __restrict__ bq,
    const float* __restrict__ wk, const float* __restrict__ bk,
    const float* __restrict__ wv, const float* __restrict__ bv)
{
    extern __shared__ __align__(16) char smem[];
    const int b   = blockIdx.z;
    const int gy  = blockIdx.y;          // 0: q+k (o 0..63); 1..4: v (64 ch each)
    const int m0  = gy * 64;             // stacked channel base
    const int n0  = blockIdx.x * 128;
    const int tid = threadIdx.x;
    const int L   = tid & 31;
    const int wid = tid >> 5;
    const int wc  = (wid & 1) * 32;      // warp m-offset (2 x 32)
    const int wn  = (wid >> 1) * 32;     // warp n-offset (4 x 32)
    const int gq  = L >> 2;
    const int tg  = L & 3;
    const bool qk = (gy == 0);

    const uint32_t sbase = smem_u32(smem);
    const __half* xhp = g_xh + ((size_t)b * NPIX + n0) * CC;
    const __half* xlp = g_xl + ((size_t)b * NPIX + n0) * CC;

    // loader: W fp32 -> split -> STS ; X via cp.async
    auto load_stage = [&](int s, int ch) {
        const int k0 = ch * 32;
        const uint32_t st = sbase + s * K1_STAGE;
        // W tile: 64 rows x 32 cols fp32. thread: row=tid>>2, 8 cols
        {
            const int row = tid >> 2, cg = (tid & 3) * 8;
            const int o = m0 + row;
            const float* wsrc;
            if (o < CQK)            wsrc = wq + (size_t)o * CC + k0 + cg;
            else if (o < 2 * CQK)   wsrc = wk + (size_t)(o - CQK) * CC + k0 + cg;
            else                    wsrc = wv + (size_t)(o - 2 * CQK) * CC + k0 + cg;
            float4 v0 = *(const float4*)(wsrc);
            float4 v1 = *(const float4*)(wsrc + 4);
            __half hb[8], lb[8];
            split_f16(v0.x, hb[0], lb[0]); split_f16(v0.y, hb[1], lb[1]);
            split_f16(v0.z, hb[2], lb[2]); split_f16(v0.w, hb[3], lb[3]);
            split_f16(v1.x, hb[4], lb[4]); split_f16(v1.y, hb[5], lb[5]);
            split_f16(v1.z, hb[6], lb[6]); split_f16(v1.w, hb[7], lb[7]);
            const uint32_t so = row * (PITCH * 2) + cg * 2;
            *(uint4*)(smem + (st - sbase) + so)          = *(const uint4*)hb;
            *(uint4*)(smem + (st - sbase) + K1_WB + so)  = *(const uint4*)lb;
        }
        // X tiles: 128 rows x 32 cols fp16 hi+lo via cp.async
        #pragma unroll
        for (int i = 0; i < 2; i++) {
            const int idx = tid + i * 256;
            const int row = idx >> 2, seg = idx & 3;
            const uint32_t so = row * (PITCH * 2) + seg * 16;
            const size_t  go = (size_t)row * CC + k0 + seg * 8;
            cp16(st + 2 * K1_WB + so, xhp + go);
            cp16(st + 2 * K1_WB + K1_XB + so, xlp + go);
        }
    };

    const uint32_t arow = (L & 15) * (PITCH * 2) + ((L >> 4) * 16);
    const uint32_t brow = ((L & 7) + ((L >> 4) << 3)) * (PITCH * 2) + (((L >> 3) & 1) * 16);

    float acc[2][4][4];
    #pragma unroll
    for (int i = 0; i < 2; i++)
        #pragma unroll
        for (int j = 0; j < 4; j++)
            #pragma unroll
            for (int r = 0; r < 4; r++) acc[i][j][r] = 0.0f;

    load_stage(0, 0); CP_COMMIT();

    for (int ch = 0; ch < K1_NCH; ch++) {
        const int s = ch & 1;
        if (ch + 1 < K1_NCH) {
            load_stage(s ^ 1, ch + 1);
            CP_COMMIT();
            CP_WAIT(1);
        } else {
            CP_WAIT(0);
        }
        __syncthreads();

        const uint32_t uWh = sbase + s * K1_STAGE;
        const uint32_t uWl = uWh + K1_WB;
        const uint32_t uXh = uWh + 2 * K1_WB;
        const uint32_t uXl = uXh + K1_XB;

        #pragma unroll
        for (int ks = 0; ks < 2; ks++) {
            const uint32_t colB = ks * 32;
            uint32_t ah[2][4], al[2][4], bh4[2][4], bl4[2][4];
            #pragma unroll
            for (int fc = 0; fc < 2; fc++) {
                const uint32_t ro = (wc + fc * 16) * (PITCH * 2) + arow + colB;
                ldsm4(ah[fc], uWh + ro);
                ldsm4(al[fc], uWl + ro);
            }
            #pragma unroll
            for (int p = 0; p < 2; p++) {
                const uint32_t ro = (wn + p * 16) * (PITCH * 2) + brow + colB;
                ldsm4(bh4[p], uXh + ro);
                if (qk) ldsm4(bl4[p], uXl + ro);
            }
            #pragma unroll
            for (int fc = 0; fc < 2; fc++)
                #pragma unroll
                for (int fm = 0; fm < 4; fm++) {
                    const uint32_t* bh = &bh4[fm >> 1][(fm & 1) * 2];
                    mma16816(acc[fc][fm], ah[fc], bh);
                    mma16816(acc[fc][fm], al[fc], bh);
                    if (qk) {
                        const uint32_t* bl = &bl4[fm >> 1][(fm & 1) * 2];
                        mma16816(acc[fc][fm], ah[fc], bl);
                    }
                }
        }
        __syncthreads();
    }

    if (qk) {
        // epilogue q/k: bias + smem transpose (pitch 129) -> [n][32] hi/lo
        float* Ts = (float*)smem;   // 64 x 129 fp32 = 33024 B < 2*K1_STAGE
        #pragma unroll
        for (int fc = 0; fc < 2; fc++) {
            #pragma unroll
            for (int fm = 0; fm < 4; fm++) {
                const int r0 = wc + fc * 16 + gq;
                const int nc = wn + fm * 8 + tg * 2;
                const float b0 = (r0 < CQK) ? bq[r0] : bk[r0 - CQK];
                const float b1 = (r0 + 8 < CQK) ? bq[r0 + 8] : bk[r0 + 8 - CQK];
                Ts[r0 * 129 + nc]           = acc[fc][fm][0] + b0;
                Ts[r0 * 129 + nc + 1]       = acc[fc][fm][1] + b0;
                Ts[(r0 + 8) * 129 + nc]     = acc[fc][fm][2] + b1;
                Ts[(r0 + 8) * 129 + nc + 1] = acc[fc][fm][3] + b1;
            }
        }
        __syncthreads();
        {
            const int n = tid >> 1;         // 0..127
            const int half = tid & 1;       // 0=q, 1=k
            __half hb[32], lb[32];
            #pragma unroll
            for (int c = 0; c < 32; c++)
                split_f16(Ts[(half * 32 + c) * 129 + n], hb[c], lb[c]);
            __half* dh = (half ? g_kh : g_qh) + ((size_t)b * NPIX + n0 + n) * CQK;
            __half* dl = (half ? g_kl : g_ql) + ((size_t)b * NPIX + n0 + n) * CQK;
            #pragma unroll
            for (int q = 0; q < 4; q++) {
                *(uint4*)(dh + q * 8) = *(const uint4*)(hb + q * 8);
                *(uint4*)(dl + q * 8) = *(const uint4*)(lb + q * 8);
            }
        }
    } else {
        // epilogue v: bias + fp16 hi write, [c][n]
        #pragma unroll
        for (int fc = 0; fc < 2; fc++) {
            #pragma unroll
            for (int fm = 0; fm < 4; fm++) {
                const int r0 = wc + fc * 16 + gq;        // local channel row
                const int nc = n0 + wn + fm * 8 + tg * 2;
                const int cA = m0 - 2 * CQK + r0;
                const int cB = cA + 8;
                {
                    __half2 h2 = __floats2half2_rn(acc[fc][fm][0] + bv[cA],
                                                   acc[fc][fm][1] + bv[cA]);
                    *(__half2*)&g_vh[((size_t)b * CC + cA) * NPIX + nc] = h2;
                }
                {
                    __half2 h2 = __floats2half2_rn(acc[fc][fm][2] + bv[cB],
                                                   acc[fc][fm][3] + bv[cB]);
                    *(__half2*)&g_vh[((size_t)b * CC + cB) * NPIX + nc] = h2;
                }
            }
        }
    }
}

// ---------------------------------------------------------------------------
// K2: energy on mma.sync fp16 (3-pass split), written transposed into at_map:
//   amap[b][m][n] = sum_c kT[m][c] * qT[n][c]
// CTA tile 128(m) x 128(n), K=32 (2 k-steps). ldmatrix fragment loads.
// ---------------------------------------------------------------------------
__global__ __launch_bounds__(256) void k_energy_mma(float* __restrict__ amap)
{
    __shared__ __align__(16) __half Kh[128 * PITCH], Kl[128 * PITCH];
    __shared__ __align__(16) __half Qh[128 * PITCH], Ql[128 * PITCH];
    const int b  = blockIdx.z;
    const int m0 = blockIdx.y * 128;
    const int n0 = blockIdx.x * 128;
    const int tid = threadIdx.x;
    const int L   = tid & 31;
    const int wid = tid >> 5;
    const int wc  = (wid & 1) * 64;     // warp m-offset
    const int wn  = (wid >> 1) * 32;    // warp n-offset
    const int gq  = L >> 2;
    const int tg  = L & 3;

    const uint32_t uKh = smem_u32(Kh), uKl = smem_u32(Kl);
    const uint32_t uQh = smem_u32(Qh), uQl = smem_u32(Ql);

    #pragma unroll
    for (int t = 0; t < 2; t++) {
        const int idx = tid + t * 256;
        const int row = idx >> 2, seg = idx & 3;
        const uint32_t so = row * (PITCH * 2) + seg * 16;
        const size_t km = ((size_t)b * NPIX + m0 + row) * CQK + seg * 8;
        const size_t qn = ((size_t)b * NPIX + n0 + row) * CQK + seg * 8;
        cp16(uKh + so, g_kh + km);
        cp16(uKl + so, g_kl + km);
        cp16(uQh + so, g_qh + qn);
        cp16(uQl + so, g_ql + qn);
    }
    CP_COMMIT(); CP_WAIT(0);
    __syncthreads();

    const uint32_t arow = (L & 15) * (PITCH * 2) + ((L >> 4) * 16);
    const uint32_t brow = ((L & 7) + ((L >> 4) << 3)) * (PITCH * 2) + (((L >> 3) & 1) * 16);

    float acc[4][4][4];
    #pragma unroll
    for (int i = 0; i < 4; i++)
        #pragma unroll
        for (int j = 0; j < 4; j++)
            #pragma unroll
            for (int r = 0; r < 4; r++) acc[i][j][r] = 0.0f;

    #pragma unroll
    for (int ks = 0; ks < 2; ks++) {
        const uint32_t colB = ks * 32;
        uint32_t ah[4][4], al[4][4], bh4[2][4], bl4[2][4];
        #pragma unroll
        for (int fc = 0; fc < 4; fc++) {
            const uint32_t ro = (wc + fc * 16) * (PITCH * 2) + arow + colB;
            ldsm4(ah[fc], uKh + ro);
            ldsm4(al[fc], uKl + ro);
        }
        #pragma unroll
        for (int p = 0; p < 2; p++) {
            const uint32_t ro = (wn + p * 16) * (PITCH * 2) + brow + colB;
            ldsm4(bh4[p], uQh + ro);
            ldsm4(bl4[p], uQl + ro);
        }
        #pragma unroll
        for (int fc = 0; fc < 4; fc++)
            #pragma unroll
            for (int fm = 0; fm < 4; fm++) {
                const uint32_t* bh = &bh4[fm >> 1][(fm & 1) * 2];
                const uint32_t* bl = &bl4[fm >> 1][(fm & 1) * 2];
                mma16816(acc[fc][fm], ah[fc], bh);
                mma16816(acc[fc][fm], ah[fc], bl);
                mma16816(acc[fc][fm], al[fc], bh);
            }
    }

    float* ab = amap + (size_t)b * NPIX * NPIX;
    #pragma unroll
    for (int fc = 0; fc < 4; fc++)
        #pragma unroll
        for (int fm = 0; fm < 4; fm++) {
            const int mr = m0 + wc + fc * 16 + gq;
            const int nc = n0 + wn + fm * 8 + tg * 2;
            *(float2*)&ab[(size_t)mr * NPIX + nc] =
                make_float2(acc[fc][fm][0], acc[fc][fm][1]);
            *(float2*)&ab[(size_t)(mr + 8) * NPIX + nc] =
                make_float2(acc[fc][fm][2], acc[fc][fm][3]);
        }
}

// ---------------------------------------------------------------------------
// K3: softmax in-place over each contiguous row amap[b][m][0..4095], plus
// streaming fp16 (hi only) copy for K4.  (~670MB total -> HBM-bound, ~optimal)
// ---------------------------------------------------------------------------
__global__ __launch_bounds__(256) void k_softmax(float* __restrict__ amap)
{
    const size_t row = blockIdx.x;
    float* p = amap + row * (size_t)NPIX;
    __half* ph = g_bh + row * (size_t)NPIX;
    const int tid = threadIdx.x;
    const int lane = tid & 31, warp = tid >> 5;
    __shared__ float red[8];

    float v[16];
    float mx = -CUDART_INF_F;
    #pragma unroll
    for (int i = 0; i < 16; i++) {
        v[i] = p[tid + i * 256];
        mx = fmaxf(mx, v[i]);
    }
    #pragma unroll
    for (int o = 16; o > 0; o >>= 1)
        mx = fmaxf(mx, __shfl_xor_sync(0xffffffffu, mx, o));
    if (lane == 0) red[warp] = mx;
    __syncthreads();
    mx = red[0];
    #pragma unroll
    for (int w = 1; w < 8; w++) mx = fmaxf(mx, red[w]);
    __syncthreads();

    float s = 0.0f;
    #pragma unroll
    for (int i = 0; i < 16; i++) {
        v[i] = __expf(v[i] - mx);
        s += v[i];
    }
    #pragma unroll
    for (int o = 16; o > 0; o >>= 1)
        s += __shfl_xor_sync(0xffffffffu, s, o);
    if (lane == 0) red[warp] = s;
    __syncthreads();
    float tot = 0.0f;
    #pragma unroll
    for (int w = 0; w < 8; w++) tot += red[w];
    float inv = 1.0f / tot;

    #pragma unroll
    for (int i = 0; i < 16; i++) {
        float a = v[i] * inv;
        p[tid + i * 256] = a;
        ph[tid + i * 256] = __float2half(a);
    }
}

// ---------------------------------------------------------------------------
// K4: sa GEMM on mma.sync fp16, 1-pass: sa = Vh*Ah (validated ~1e-5 rel_err).
//   out[b][c][m] = x[b][c][m] + gamma * sum_n v[b][c][n] * amap[b][m][n]
// CTA tile 128(c) x 128(m), K chunk 32, 3-stage cp.async pipeline.
// ---------------------------------------------------------------------------
#define BKC   32
#define TILE_BYTES (128 * PITCH * 2)        // 10240
#define STAGE_B    (2 * TILE_BYTES)         // 20480: Vh | Ah
#define NSTAGE 3
#define NCH   (NPIX / BKC)                  // 128

__global__ __launch_bounds__(256) void k_out_mma(
    const float* __restrict__ x, const float* __restrict__ gamma,
    float* __restrict__ out)
{
    extern __shared__ __align__(16) char smem[];
    const int b  = blockIdx.z;
    const int c0 = blockIdx.y * 128;
    const int m0 = blockIdx.x * 128;
    const int tid = threadIdx.x;
    const int L   = tid & 31;
    const int wid = tid >> 5;
    const int wc  = (wid & 1) * 64;     // warp c-offset
    const int wm  = (wid >> 1) * 32;    // warp m-offset
    const int gq  = L >> 2;
    const int tg  = L & 3;

    const uint32_t sbase = smem_u32(smem);
    const __half* vhp = g_vh + ((size_t)b * CC + c0) * NPIX;
    const __half* bhp = g_bh + ((size_t)b * NPIX + m0) * NPIX;

    auto load_stage = [&](int s, int ch) {
        const int k0 = ch * BKC;
        const uint32_t st = sbase + s * STAGE_B;
        #pragma unroll
        for (int i = 0; i < 2; i++) {
            const int idx = tid + i * 256;
            const int row = idx >> 2;
            const int seg = idx & 3;
            const uint32_t so = row * (PITCH * 2) + seg * 16;
            const size_t  go = (size_t)row * NPIX + k0 + seg * 8;
            cp16(st + 0 * TILE_BYTES + so, vhp + go);
            cp16(st + 1 * TILE_BYTES + so, bhp + go);
        }
    };

    const uint32_t arow = (L & 15) * (PITCH * 2) + ((L >> 4) * 16);
    const uint32_t brow = ((L & 7) + ((L >> 4) << 3)) * (PITCH * 2) + (((L >> 3) & 1) * 16);

    float acc[4][4][4];
    #pragma unroll
    for (int i = 0; i < 4; i++)
        #pragma unroll
        for (int j = 0; j < 4; j++)
            #pragma unroll
            for (int r = 0; r < 4; r++) acc[i][j][r] = 0.0f;

    load_stage(0, 0); CP_COMMIT();
    load_stage(1, 1); CP_COMMIT();

    for (int ch = 0; ch < NCH; ch++) {
        const int s = ch % NSTAGE;
        if (ch + 1 < NCH) CP_WAIT(1); else CP_WAIT(0);
        __syncthreads();

        const uint32_t uVh = sbase + s * STAGE_B;
        const uint32_t uAh = uVh + TILE_BYTES;

        #pragma unroll
        for (int ks = 0; ks < 2; ks++) {
            const uint32_t colB = ks * 32;
            uint32_t vh[4][4], bh4[2][4];
            #pragma unroll
            for (int fc = 0; fc < 4; fc++) {
                const uint32_t ro = (wc + fc * 16) * (PITCH * 2) + arow + colB;
                ldsm4(vh[fc], uVh + ro);
            }
            #pragma unroll
            for (int p = 0; p < 2; p++) {
                const uint32_t ro = (wm + p * 16) * (PITCH * 2) + brow + colB;
                ldsm4(bh4[p], uAh + ro);
            }
            #pragma unroll
            for (int fc = 0; fc < 4; fc++)
                #pragma unroll
                for (int fm = 0; fm < 4; fm++) {
                    const uint32_t* bh = &bh4[fm >> 1][(fm & 1) * 2];
                    mma16816(acc[fc][fm], vh[fc], bh);
                }
        }

        if (ch + 2 < NCH) {
            load_stage((ch + 2) % NSTAGE, ch + 2);
            CP_COMMIT();
        }
    }

    const float gm = gamma[0];
    #pragma unroll
    for (int fc = 0; fc < 4; fc++) {
        #pragma unroll
        for (int fm = 0; fm < 4; fm++) {
            const int cr = c0 + wc + fc * 16 + gq;
            const int mc = m0 + wm + fm * 8 + tg * 2;
            {
                const size_t gi = ((size_t)b * CC + cr) * NPIX + mc;
                float2 xv = *(const float2*)&x[gi];
                float2 o;
                o.x = xv.x + gm * acc[fc][fm][0];
                o.y = xv.y + gm * acc[fc][fm][1];
                *(float2*)&out[gi] = o;
            }
            {
                const size_t gi = ((size_t)b * CC + cr + 8) * NPIX + mc;
                float2 xv = *(const float2*)&x[gi];
                float2 o;
                o.x = xv.x + gm * acc[fc][fm][2];
                o.y = xv.y + gm * acc[fc][fm][3];
                *(float2*)&out[gi] = o;
            }
        }
    }
}

extern "C" void kernel_launch(void* const* d_in, const int* in_sizes, int n_in,
                              void* d_out, int out_size)
{
    (void)in_sizes; (void)n_in; (void)out_size;
    const float* x     = (const float*)d_in[0];
    const float* wq    = (const float*)d_in[1];
    const float* bq    = (const float*)d_in[2];
    const float* wk    = (const float*)d_in[3];
    const float* bk    = (const float*)d_in[4];
    const float* wv    = (const float*)d_in[5];
    const float* bv    = (const float*)d_in[6];
    const float* gamma = (const float*)d_in[7];

    float* out  = (float*)d_out;                      // [B,C,H,W]
    float* amap = out + (size_t)BB * CC * NPIX;       // [B,N,N]

    static const int dsm_k4 = NSTAGE * STAGE_B;       // 61440 B
    static const int dsm_k1 = 2 * K1_STAGE;           // 61440 B
    cudaFuncSetAttribute(k_out_mma, cudaFuncAttributeMaxDynamicSharedMemorySize, dsm_k4);
    cudaFuncSetAttribute(k_qkv_mma, cudaFuncAttributeMaxDynamicSharedMemorySize, dsm_k1);

    k_xsplit<<<dim3(NPIX / 64, CC / 64, BB), 256>>>(x);
    k_qkv_mma<<<dim3(NPIX / 128, 5, BB), 256, dsm_k1>>>(wq, bq, wk, bk, wv, bv);
    k_energy_mma<<<dim3(NPIX / 128, NPIX / 128, BB), 256>>>(amap);
    k_softmax<<<dim3(BB * NPIX), 256>>>(amap);
    k_out_mma<<<dim3(NPIX / 128, CC / 128, BB), 256, dsm_k4>>>(x, gamma, out);
}

// round 17
// speedup vs baseline: 6.5404x; 1.0540x over previous
#include <cuda_runtime.h>
#include <cuda_fp16.h>
#include <math_constants.h>
#include <cstdint>

// Problem constants: B=4, C=256, H=W=64 -> N=4096 pixels, Cqk=C/8=32
#define BB    4
#define CC    256
#define CQK   32
#define NPIX  4096

// Scratch (no cudaMalloc allowed). fp16 hi/lo splits (11-bit mantissa each).
__device__ __align__(16) __half g_xh[(size_t)BB * NPIX * CC];
__device__ __align__(16) __half g_xl[(size_t)BB * NPIX * CC];
__device__ __align__(16) __half g_qh[BB * NPIX * CQK];
__device__ __align__(16) __half g_ql[BB * NPIX * CQK];
__device__ __align__(16) __half g_kh[BB * NPIX * CQK];
__device__ __align__(16) __half g_kl[BB * NPIX * CQK];
__device__ __align__(16) __half g_vh[BB * CC * NPIX];
// attn fp16 (hi only) — K4 is 1-pass: Vh*Ah
__device__ __align__(16) __half g_bh[(size_t)BB * NPIX * NPIX];
// softmax row partial sums [b][m][ntile=32] and reciprocal row sums [b][m]
__device__ __align__(16) float g_psum[(size_t)BB * NPIX * 32];
__device__ __align__(16) float g_rinv[BB * NPIX];

// ===========================================================================
// PTX helpers — baseline (non-'a') features only: mma.sync f16, ldmatrix,
// cp.async. tcgen05/TMEM rejected by ptxas at compute_103 (no 'a').
// ===========================================================================
__device__ __forceinline__ void mma16816(float* d, const uint32_t* a, const uint32_t* b) {
    asm volatile(
        "mma.sync.aligned.m16n8k16.row.col.f32.f16.f16.f32 "
        "{%0,%1,%2,%3}, {%4,%5,%6,%7}, {%8,%9}, {%0,%1,%2,%3};"
        : "+f"(d[0]), "+f"(d[1]), "+f"(d[2]), "+f"(d[3])
        : "r"(a[0]), "r"(a[1]), "r"(a[2]), "r"(a[3]), "r"(b[0]), "r"(b[1]));
}
__device__ __forceinline__ void ldsm4(uint32_t* r, uint32_t addr) {
    asm volatile("ldmatrix.sync.aligned.m8n8.x4.shared.b16 {%0,%1,%2,%3}, [%4];"
        : "=r"(r[0]), "=r"(r[1]), "=r"(r[2]), "=r"(r[3]) : "r"(addr));
}
__device__ __forceinline__ uint32_t smem_u32(const void* p) {
    uint32_t a;
    asm("{ .reg .u64 t; cvta.to.shared.u64 t, %1; cvt.u32.u64 %0, t; }"
        : "=r"(a) : "l"(p));
    return a;
}
__device__ __forceinline__ void cp16(uint32_t saddr, const void* g) {
    asm volatile("cp.async.cg.shared.global [%0], [%1], 16;" :: "r"(saddr), "l"(g));
}
#define CP_COMMIT() asm volatile("cp.async.commit_group;" ::: "memory")
#define CP_WAIT(n)  asm volatile("cp.async.wait_group %0;" :: "n"(n) : "memory")

__device__ __forceinline__ void split_f16(float v, __half& h, __half& l) {
    h = __float2half(v);
    l = __float2half(v - __half2float(h));
}

#define PITCH 40   // b16 elements per smem row (80B) — conflict-free ldmatrix

// ---------------------------------------------------------------------------
// K0: transpose + fp16 hi/lo split of x:  [b][c][n] fp32 -> [b][n][c] fp16 x2
// ---------------------------------------------------------------------------
__global__ __launch_bounds__(256) void k_xsplit(const float* __restrict__ x)
{
    __shared__ float Ts[64][65];
    const int b  = blockIdx.z;
    const int c0 = blockIdx.y * 64;
    const int n0 = blockIdx.x * 64;
    const int tid = threadIdx.x;

    {
        const int r = tid >> 2, f0 = (tid & 3) * 4;
        const float* src = x + ((size_t)b * CC + c0 + r) * NPIX + n0;
        #pragma unroll
        for (int j = 0; j < 4; j++) {
            float4 v = *(const float4*)(src + (f0 + j) * 4);
            Ts[r][(f0 + j) * 4 + 0] = v.x;
            Ts[r][(f0 + j) * 4 + 1] = v.y;
            Ts[r][(f0 + j) * 4 + 2] = v.z;
            Ts[r][(f0 + j) * 4 + 3] = v.w;
        }
    }
    __syncthreads();
    {
        const int n = tid >> 2, cg = (tid & 3) * 16;
        __half hb[16], lb[16];
        #pragma unroll
        for (int cc = 0; cc < 16; cc++)
            split_f16(Ts[cg + cc][n], hb[cc], lb[cc]);
        __half* dh = g_xh + ((size_t)b * NPIX + n0 + n) * CC + c0 + cg;
        __half* dl = g_xl + ((size_t)b * NPIX + n0 + n) * CC + c0 + cg;
        *(uint4*)(dh)     = *(const uint4*)(hb);
        *(uint4*)(dh + 8) = *(const uint4*)(hb + 8);
        *(uint4*)(dl)     = *(const uint4*)(lb);
        *(uint4*)(dl + 8) = *(const uint4*)(lb + 8);
    }
}

// ---------------------------------------------------------------------------
// K1: QKV projection on mma.sync fp16 (unchanged from R15).
// ---------------------------------------------------------------------------
#define K1_WB   (64 * PITCH * 2)
#define K1_XB   (128 * PITCH * 2)
#define K1_STAGE (2 * K1_WB + 2 * K1_XB)
#define K1_NCH  (CC / 32)

__global__ __launch_bounds__(256) void k_qkv_mma(
    const float* __restrict__ wq, const float* __restrict__ bq,
    const float* __restrict__ wk, const float* __restrict__ bk,
    const float* __restrict__ wv, const float* __restrict__ bv)
{
    extern __shared__ __align__(16) char smem[];
    const int b   = blockIdx.z;
    const int gy  = blockIdx.y;
    const int m0  = gy * 64;
    const int n0  = blockIdx.x * 128;
    const int tid = threadIdx.x;
    const int L   = tid & 31;
    const int wid = tid >> 5;
    const int wc  = (wid & 1) * 32;
    const int wn  = (wid >> 1) * 32;
    const int gq  = L >> 2;
    const int tg  = L & 3;
    const bool qk = (gy == 0);

    const uint32_t sbase = smem_u32(smem);
    const __half* xhp = g_xh + ((size_t)b * NPIX + n0) * CC;
    const __half* xlp = g_xl + ((size_t)b * NPIX + n0) * CC;

    auto load_stage = [&](int s, int ch) {
        const int k0 = ch * 32;
        const uint32_t st = sbase + s * K1_STAGE;
        {
            const int row = tid >> 2, cg = (tid & 3) * 8;
            const int o = m0 + row;
            const float* wsrc;
            if (o < CQK)            wsrc = wq + (size_t)o * CC + k0 + cg;
            else if (o < 2 * CQK)   wsrc = wk + (size_t)(o - CQK) * CC + k0 + cg;
            else                    wsrc = wv + (size_t)(o - 2 * CQK) * CC + k0 + cg;
            float4 v0 = *(const float4*)(wsrc);
            float4 v1 = *(const float4*)(wsrc + 4);
            __half hb[8], lb[8];
            split_f16(v0.x, hb[0], lb[0]); split_f16(v0.y, hb[1], lb[1]);
            split_f16(v0.z, hb[2], lb[2]); split_f16(v0.w, hb[3], lb[3]);
            split_f16(v1.x, hb[4], lb[4]); split_f16(v1.y, hb[5], lb[5]);
            split_f16(v1.z, hb[6], lb[6]); split_f16(v1.w, hb[7], lb[7]);
            const uint32_t so = row * (PITCH * 2) + cg * 2;
            *(uint4*)(smem + (st - sbase) + so)          = *(const uint4*)hb;
            *(uint4*)(smem + (st - sbase) + K1_WB + so)  = *(const uint4*)lb;
        }
        #pragma unroll
        for (int i = 0; i < 2; i++) {
            const int idx = tid + i * 256;
            const int row = idx >> 2, seg = idx & 3;
            const uint32_t so = row * (PITCH * 2) + seg * 16;
            const size_t  go = (size_t)row * CC + k0 + seg * 8;
            cp16(st + 2 * K1_WB + so, xhp + go);
            cp16(st + 2 * K1_WB + K1_XB + so, xlp + go);
        }
    };

    const uint32_t arow = (L & 15) * (PITCH * 2) + ((L >> 4) * 16);
    const uint32_t brow = ((L & 7) + ((L >> 4) << 3)) * (PITCH * 2) + (((L >> 3) & 1) * 16);

    float acc[2][4][4];
    #pragma unroll
    for (int i = 0; i < 2; i++)
        #pragma unroll
        for (int j = 0; j < 4; j++)
            #pragma unroll
            for (int r = 0; r < 4; r++) acc[i][j][r] = 0.0f;

    load_stage(0, 0); CP_COMMIT();

    for (int ch = 0; ch < K1_NCH; ch++) {
        const int s = ch & 1;
        if (ch + 1 < K1_NCH) {
            load_stage(s ^ 1, ch + 1);
            CP_COMMIT();
            CP_WAIT(1);
        } else {
            CP_WAIT(0);
        }
        __syncthreads();

        const uint32_t uWh = sbase + s * K1_STAGE;
        const uint32_t uWl = uWh + K1_WB;
        const uint32_t uXh = uWh + 2 * K1_WB;
        const uint32_t uXl = uXh + K1_XB;

        #pragma unroll
        for (int ks = 0; ks < 2; ks++) {
            const uint32_t colB = ks * 32;
            uint32_t ah[2][4], al[2][4], bh4[2][4], bl4[2][4];
            #pragma unroll
            for (int fc = 0; fc < 2; fc++) {
                const uint32_t ro = (wc + fc * 16) * (PITCH * 2) + arow + colB;
                ldsm4(ah[fc], uWh + ro);
                ldsm4(al[fc], uWl + ro);
            }
            #pragma unroll
            for (int p = 0; p < 2; p++) {
                const uint32_t ro = (wn + p * 16) * (PITCH * 2) + brow + colB;
                ldsm4(bh4[p], uXh + ro);
                if (qk) ldsm4(bl4[p], uXl + ro);
            }
            #pragma unroll
            for (int fc = 0; fc < 2; fc++)
                #pragma unroll
                for (int fm = 0; fm < 4; fm++) {
                    const uint32_t* bh = &bh4[fm >> 1][(fm & 1) * 2];
                    mma16816(acc[fc][fm], ah[fc], bh);
                    mma16816(acc[fc][fm], al[fc], bh);
                    if (qk) {
                        const uint32_t* bl = &bl4[fm >> 1][(fm & 1) * 2];
                        mma16816(acc[fc][fm], ah[fc], bl);
                    }
                }
        }
        __syncthreads();
    }

    if (qk) {
        float* Ts = (float*)smem;
        #pragma unroll
        for (int fc = 0; fc < 2; fc++) {
            #pragma unroll
            for (int fm = 0; fm < 4; fm++) {
                const int r0 = wc + fc * 16 + gq;
                const int nc = wn + fm * 8 + tg * 2;
                const float b0 = (r0 < CQK) ? bq[r0] : bk[r0 - CQK];
                const float b1 = (r0 + 8 < CQK) ? bq[r0 + 8] : bk[r0 + 8 - CQK];
                Ts[r0 * 129 + nc]           = acc[fc][fm][0] + b0;
                Ts[r0 * 129 + nc + 1]       = acc[fc][fm][1] + b0;
                Ts[(r0 + 8) * 129 + nc]     = acc[fc][fm][2] + b1;
                Ts[(r0 + 8) * 129 + nc + 1] = acc[fc][fm][3] + b1;
            }
        }
        __syncthreads();
        {
            const int n = tid >> 1;
            const int half = tid & 1;
            __half hb[32], lb[32];
            #pragma unroll
            for (int c = 0; c < 32; c++)
                split_f16(Ts[(half * 32 + c) * 129 + n], hb[c], lb[c]);
            __half* dh = (half ? g_kh : g_qh) + ((size_t)b * NPIX + n0 + n) * CQK;
            __half* dl = (half ? g_kl : g_ql) + ((size_t)b * NPIX + n0 + n) * CQK;
            #pragma unroll
            for (int q = 0; q < 4; q++) {
                *(uint4*)(dh + q * 8) = *(const uint4*)(hb + q * 8);
                *(uint4*)(dl + q * 8) = *(const uint4*)(lb + q * 8);
            }
        }
    } else {
        #pragma unroll
        for (int fc = 0; fc < 2; fc++) {
            #pragma unroll
            for (int fm = 0; fm < 4; fm++) {
                const int r0 = wc + fc * 16 + gq;
                const int nc = n0 + wn + fm * 8 + tg * 2;
                const int cA = m0 - 2 * CQK + r0;
                const int cB = cA + 8;
                {
                    __half2 h2 = __floats2half2_rn(acc[fc][fm][0] + bv[cA],
                                                   acc[fc][fm][1] + bv[cA]);
                    *(__half2*)&g_vh[((size_t)b * CC + cA) * NPIX + nc] = h2;
                }
                {
                    __half2 h2 = __floats2half2_rn(acc[fc][fm][2] + bv[cB],
                                                   acc[fc][fm][3] + bv[cB]);
                    *(__half2*)&g_vh[((size_t)b * CC + cB) * NPIX + nc] = h2;
                }
            }
        }
    }
}

// ---------------------------------------------------------------------------
// K2 (two passes): energy GEMM + streaming softmax, NO energy materialization.
//   amap[b][m][n] = softmax_n( sum_c kT[m][c] * qT[n][c] )
// Energy ~N(0,32), |e|max ~31 << 88: exp without max-subtraction is fp32-safe.
// PASS 1: GEMM -> __expf -> per-row partial sums -> g_psum[b][m][ntile]
// PASS 2: identical GEMM+__expf (bitwise same) * g_rinv[m] -> amap fp32 + g_bh fp16
// ---------------------------------------------------------------------------
template <int PASS>
__global__ __launch_bounds__(256) void k_energy_sm(float* __restrict__ amap)
{
    __shared__ __align__(16) __half Kh[128 * PITCH], Kl[128 * PITCH];
    __shared__ __align__(16) __half Qh[128 * PITCH], Ql[128 * PITCH];
    __shared__ float Ps[128][5];
    const int b  = blockIdx.z;
    const int m0 = blockIdx.y * 128;
    const int n0 = blockIdx.x * 128;
    const int tid = threadIdx.x;
    const int L   = tid & 31;
    const int wid = tid >> 5;
    const int wc  = (wid & 1) * 64;     // warp m-offset
    const int wn  = (wid >> 1) * 32;    // warp n-offset
    const int gq  = L >> 2;
    const int tg  = L & 3;

    const uint32_t uKh = smem_u32(Kh), uKl = smem_u32(Kl);
    const uint32_t uQh = smem_u32(Qh), uQl = smem_u32(Ql);

    #pragma unroll
    for (int t = 0; t < 2; t++) {
        const int idx = tid + t * 256;
        const int row = idx >> 2, seg = idx & 3;
        const uint32_t so = row * (PITCH * 2) + seg * 16;
        const size_t km = ((size_t)b * NPIX + m0 + row) * CQK + seg * 8;
        const size_t qn = ((size_t)b * NPIX + n0 + row) * CQK + seg * 8;
        cp16(uKh + so, g_kh + km);
        cp16(uKl + so, g_kl + km);
        cp16(uQh + so, g_qh + qn);
        cp16(uQl + so, g_ql + qn);
    }
    CP_COMMIT(); CP_WAIT(0);
    __syncthreads();

    const uint32_t arow = (L & 15) * (PITCH * 2) + ((L >> 4) * 16);
    const uint32_t brow = ((L & 7) + ((L >> 4) << 3)) * (PITCH * 2) + (((L >> 3) & 1) * 16);

    float acc[4][4][4];
    #pragma unroll
    for (int i = 0; i < 4; i++)
        #pragma unroll
        for (int j = 0; j < 4; j++)
            #pragma unroll
            for (int r = 0; r < 4; r++) acc[i][j][r] = 0.0f;

    #pragma unroll
    for (int ks = 0; ks < 2; ks++) {
        const uint32_t colB = ks * 32;
        uint32_t ah[4][4], al[4][4], bh4[2][4], bl4[2][4];
        #pragma unroll
        for (int fc = 0; fc < 4; fc++) {
            const uint32_t ro = (wc + fc * 16) * (PITCH * 2) + arow + colB;
            ldsm4(ah[fc], uKh + ro);
            ldsm4(al[fc], uKl + ro);
        }
        #pragma unroll
        for (int p = 0; p < 2; p++) {
            const uint32_t ro = (wn + p * 16) * (PITCH * 2) + brow + colB;
            ldsm4(bh4[p], uQh + ro);
            ldsm4(bl4[p], uQl + ro);
        }
        #pragma unroll
        for (int fc = 0; fc < 4; fc++)
            #pragma unroll
            for (int fm = 0; fm < 4; fm++) {
                const uint32_t* bh = &bh4[fm >> 1][(fm & 1) * 2];
                const uint32_t* bl = &bl4[fm >> 1][(fm & 1) * 2];
                mma16816(acc[fc][fm], ah[fc], bh);
                mma16816(acc[fc][fm], ah[fc], bl);
                mma16816(acc[fc][fm], al[fc], bh);
            }
    }

    if (PASS == 1) {
        // exp + row-sum over this CTA's 128 n-cols
        float s[4][2];
        #pragma unroll
        for (int fc = 0; fc < 4; fc++) { s[fc][0] = 0.0f; s[fc][1] = 0.0f; }
        #pragma unroll
        for (int fc = 0; fc < 4; fc++)
            #pragma unroll
            for (int fm = 0; fm < 4; fm++) {
                s[fc][0] += __expf(acc[fc][fm][0]) + __expf(acc[fc][fm][1]);
                s[fc][1] += __expf(acc[fc][fm][2]) + __expf(acc[fc][fm][3]);
            }
        #pragma unroll
        for (int fc = 0; fc < 4; fc++)
            #pragma unroll
            for (int j = 0; j < 2; j++) {
                float v = s[fc][j];
                v += __shfl_xor_sync(0xffffffffu, v, 1);
                v += __shfl_xor_sync(0xffffffffu, v, 2);
                if (tg == 0) Ps[wc + fc * 16 + j * 8 + gq][wid >> 1] = v;
            }
        __syncthreads();
        if (tid < 128) {
            float t = Ps[tid][0] + Ps[tid][1] + Ps[tid][2] + Ps[tid][3];
            g_psum[((size_t)b * NPIX + m0 + tid) * 32 + blockIdx.x] = t;
        }
    } else {
        // exp * rinv -> amap fp32 + g_bh fp16
        float* ab = amap + (size_t)b * NPIX * NPIX;
        __half* hb = g_bh + (size_t)b * NPIX * NPIX;
        #pragma unroll
        for (int fc = 0; fc < 4; fc++) {
            const int mr = m0 + wc + fc * 16 + gq;
            const float i1 = g_rinv[b * NPIX + mr];
            const float i2 = g_rinv[b * NPIX + mr + 8];
            #pragma unroll
            for (int fm = 0; fm < 4; fm++) {
                const int nc = n0 + wn + fm * 8 + tg * 2;
                float p0 = __expf(acc[fc][fm][0]) * i1;
                float p1 = __expf(acc[fc][fm][1]) * i1;
                float p2 = __expf(acc[fc][fm][2]) * i2;
                float p3 = __expf(acc[fc][fm][3]) * i2;
                *(float2*)&ab[(size_t)mr * NPIX + nc]       = make_float2(p0, p1);
                *(float2*)&ab[(size_t)(mr + 8) * NPIX + nc] = make_float2(p2, p3);
                *(__half2*)&hb[(size_t)mr * NPIX + nc]       = __floats2half2_rn(p0, p1);
                *(__half2*)&hb[(size_t)(mr + 8) * NPIX + nc] = __floats2half2_rn(p2, p3);
            }
        }
    }
}

// ---------------------------------------------------------------------------
// K2r: reduce 32 partials per row -> reciprocal row sum.
// ---------------------------------------------------------------------------
__global__ __launch_bounds__(256) void k_rowsum()
{
    const int row = blockIdx.x * 256 + threadIdx.x;   // 0..16383
    const float4* p = (const float4*)(g_psum + (size_t)row * 32);
    float s = 0.0f;
    #pragma unroll
    for (int i = 0; i < 8; i++) {
        float4 v = p[i];
        s += (v.x + v.y) + (v.z + v.w);
    }
    g_rinv[row] = 1.0f / s;
}

// ---------------------------------------------------------------------------
// K4: sa GEMM on mma.sync fp16, 1-pass: sa = Vh*Ah (unchanged from R15).
// ---------------------------------------------------------------------------
#define BKC   32
#define TILE_BYTES (128 * PITCH * 2)
#define STAGE_B    (2 * TILE_BYTES)
#define NSTAGE 3
#define NCH   (NPIX / BKC)

__global__ __launch_bounds__(256) void k_out_mma(
    const float* __restrict__ x, const float* __restrict__ gamma,
    float* __restrict__ out)
{
    extern __shared__ __align__(16) char smem[];
    const int b  = blockIdx.z;
    const int c0 = blockIdx.y * 128;
    const int m0 = blockIdx.x * 128;
    const int tid = threadIdx.x;
    const int L   = tid & 31;
    const int wid = tid >> 5;
    const int wc  = (wid & 1) * 64;
    const int wm  = (wid >> 1) * 32;
    const int gq  = L >> 2;
    const int tg  = L & 3;

    const uint32_t sbase = smem_u32(smem);
    const __half* vhp = g_vh + ((size_t)b * CC + c0) * NPIX;
    const __half* bhp = g_bh + ((size_t)b * NPIX + m0) * NPIX;

    auto load_stage = [&](int s, int ch) {
        const int k0 = ch * BKC;
        const uint32_t st = sbase + s * STAGE_B;
        #pragma unroll
        for (int i = 0; i < 2; i++) {
            const int idx = tid + i * 256;
            const int row = idx >> 2;
            const int seg = idx & 3;
            const uint32_t so = row * (PITCH * 2) + seg * 16;
            const size_t  go = (size_t)row * NPIX + k0 + seg * 8;
            cp16(st + 0 * TILE_BYTES + so, vhp + go);
            cp16(st + 1 * TILE_BYTES + so, bhp + go);
        }
    };

    const uint32_t arow = (L & 15) * (PITCH * 2) + ((L >> 4) * 16);
    const uint32_t brow = ((L & 7) + ((L >> 4) << 3)) * (PITCH * 2) + (((L >> 3) & 1) * 16);

    float acc[4][4][4];
    #pragma unroll
    for (int i = 0; i < 4; i++)
        #pragma unroll
        for (int j = 0; j < 4; j++)
            #pragma unroll
            for (int r = 0; r < 4; r++) acc[i][j][r] = 0.0f;

    load_stage(0, 0); CP_COMMIT();
    load_stage(1, 1); CP_COMMIT();

    for (int ch = 0; ch < NCH; ch++) {
        const int s = ch % NSTAGE;
        if (ch + 1 < NCH) CP_WAIT(1); else CP_WAIT(0);
        __syncthreads();

        const uint32_t uVh = sbase + s * STAGE_B;
        const uint32_t uAh = uVh + TILE_BYTES;

        #pragma unroll
        for (int ks = 0; ks < 2; ks++) {
            const uint32_t colB = ks * 32;
            uint32_t vh[4][4], bh4[2][4];
            #pragma unroll
            for (int fc = 0; fc < 4; fc++) {
                const uint32_t ro = (wc + fc * 16) * (PITCH * 2) + arow + colB;
                ldsm4(vh[fc], uVh + ro);
            }
            #pragma unroll
            for (int p = 0; p < 2; p++) {
                const uint32_t ro = (wm + p * 16) * (PITCH * 2) + brow + colB;
                ldsm4(bh4[p], uAh + ro);
            }
            #pragma unroll
            for (int fc = 0; fc < 4; fc++)
                #pragma unroll
                for (int fm = 0; fm < 4; fm++) {
                    const uint32_t* bh = &bh4[fm >> 1][(fm & 1) * 2];
                    mma16816(acc[fc][fm], vh[fc], bh);
                }
        }

        if (ch + 2 < NCH) {
            load_stage((ch + 2) % NSTAGE, ch + 2);
            CP_COMMIT();
        }
    }

    const float gm = gamma[0];
    #pragma unroll
    for (int fc = 0; fc < 4; fc++) {
        #pragma unroll
        for (int fm = 0; fm < 4; fm++) {
            const int cr = c0 + wc + fc * 16 + gq;
            const int mc = m0 + wm + fm * 8 + tg * 2;
            {
                const size_t gi = ((size_t)b * CC + cr) * NPIX + mc;
                float2 xv = *(const float2*)&x[gi];
                float2 o;
                o.x = xv.x + gm * acc[fc][fm][0];
                o.y = xv.y + gm * acc[fc][fm][1];
                *(float2*)&out[gi] = o;
            }
            {
                const size_t gi = ((size_t)b * CC + cr + 8) * NPIX + mc;
                float2 xv = *(const float2*)&x[gi];
                float2 o;
                o.x = xv.x + gm * acc[fc][fm][2];
                o.y = xv.y + gm * acc[fc][fm][3];
                *(float2*)&out[gi] = o;
            }
        }
    }
}

extern "C" void kernel_launch(void* const* d_in, const int* in_sizes, int n_in,
                              void* d_out, int out_size)
{
    (void)in_sizes; (void)n_in; (void)out_size;
    const float* x     = (const float*)d_in[0];
    const float* wq    = (const float*)d_in[1];
    const float* bq    = (const float*)d_in[2];
    const float* wk    = (const float*)d_in[3];
    const float* bk    = (const float*)d_in[4];
    const float* wv    = (const float*)d_in[5];
    const float* bv    = (const float*)d_in[6];
    const float* gamma = (const float*)d_in[7];

    float* out  = (float*)d_out;                      // [B,C,H,W]
    float* amap = out + (size_t)BB * CC * NPIX;       // [B,N,N]

    static const int dsm_k4 = NSTAGE * STAGE_B;       // 61440 B
    static const int dsm_k1 = 2 * K1_STAGE;           // 61440 B
    cudaFuncSetAttribute(k_out_mma, cudaFuncAttributeMaxDynamicSharedMemorySize, dsm_k4);
    cudaFuncSetAttribute(k_qkv_mma, cudaFuncAttributeMaxDynamicSharedMemorySize, dsm_k1);

    k_xsplit<<<dim3(NPIX / 64, CC / 64, BB), 256>>>(x);
    k_qkv_mma<<<dim3(NPIX / 128, 5, BB), 256, dsm_k1>>>(wq, bq, wk, bk, wv, bv);
    k_energy_sm<1><<<dim3(NPIX / 128, NPIX / 128, BB), 256>>>(amap);
    k_rowsum<<<dim3(BB * NPIX / 256), 256>>>();
    k_energy_sm<2><<<dim3(NPIX / 128, NPIX / 128, BB), 256>>>(amap);
    k_out_mma<<<dim3(NPIX / 128, CC / 128, BB), 256, dsm_k4>>>(x, gamma, out);
}